// round 8
// baseline (speedup 1.0000x reference)
#include <cuda_runtime.h>
#include <cstdint>

// Problem constants
#define N_NODES 100000
#define F_INPUT 128
#define E_EDGES 1200000
#define B_GRAPHS 8
#define NE      (E_EDGES + N_NODES)
#define NEG_SLOPE 0.2f
#define EPS_GN   1e-5f
#define NBLK     ((N_NODES + 255) / 256)   // 391

// -------------------- scratch (static device globals; no allocs) ------------
__device__ float g_xl[N_NODES * 256];       // [N, H*C]
__device__ float g_resid[N_NODES * 64];     // x @ res_W^T
__device__ float g_asrc[N_NODES * 4];
__device__ float g_adst[N_NODES * 4];
__device__ float g_acc[N_NODES * 64];       // final h (pre-norm)
__device__ int   g_cnt[N_NODES];            // in-degree (excl. self loop)
__device__ int   g_off[N_NODES + 1];        // CSR offsets
__device__ int   g_pos[N_NODES];            // fill cursors
__device__ int   g_srcs[E_EDGES];           // src ids bucketed by dst
__device__ int   g_bsum[NBLK];              // per-block counts -> prefix
__device__ int   g_start[B_GRAPHS + 1];
__device__ float g_ms[B_GRAPHS * 64];
__device__ float g_inv[B_GRAPHS * 64];
__device__ int   g_idx64;

// -------------------- generic helpers ---------------------------------------
__device__ __forceinline__ int load_idx(const void* p, long long i) {
    if (g_idx64) return (int)((const long long*)p)[i];
    return ((const int*)p)[i];
}

// m16n8k8 tf32 mma (legacy tensor path; plain sm_80+ PTX)
#define MMA_TF32(c, a, b) \
    asm volatile("mma.sync.aligned.m16n8k8.row.col.f32.tf32.tf32.f32 " \
        "{%0,%1,%2,%3}, {%4,%5,%6,%7}, {%8,%9}, {%0,%1,%2,%3};" \
        : "+f"((c)[0]), "+f"((c)[1]), "+f"((c)[2]), "+f"((c)[3]) \
        : "r"((a)[0]), "r"((a)[1]), "r"((a)[2]), "r"((a)[3]), \
          "r"((b)[0]), "r"((b)[1]))

// -------------------- 0: dtype detection -------------------------------------
__global__ void k_detect(const void* ei_raw) {
    if (threadIdx.x == 0 && blockIdx.x == 0) {
        const int* p = (const int*)ei_raw;
        int is64 = 1;
        #pragma unroll 1
        for (int i = 0; i < 64; i++)
            if (p[2 * i + 1] != 0) { is64 = 0; break; }
        g_idx64 = is64;
    }
}

// -------------------- 1: zero counters ---------------------------------------
__global__ void k_zero() {
    int i = blockIdx.x * blockDim.x + threadIdx.x;
    if (i < N_NODES) g_cnt[i] = 0;
}

// -------------------- 2: tf32 mma.sync GEMM + fused attn logits --------------
// CTA = 128 rows x 64 cols, full K=128 in SMEM. grid.y 0..3 -> heads, 4 -> resW.
// 3xTF32 split: acc += Alo*Bhi + Ahi*Blo + Ahi*Bhi.
#define GM_LDA 132
#define GM_SMEM ((128 + 64) * GM_LDA * 4)

__global__ void __launch_bounds__(256, 2) k_gemm_mma(
    const float* __restrict__ x, const float* __restrict__ W,
    const float* __restrict__ resW,
    const float* __restrict__ att_src, const float* __restrict__ att_dst)
{
    extern __shared__ __align__(16) float smem[];
    float* As = smem;
    float* Bs = smem + 128 * GM_LDA;
    int tid = threadIdx.x, lane = tid & 31, wid = tid >> 5;
    int warp_m = wid >> 2, warp_n = wid & 3;
    int m0 = blockIdx.x * 128;
    int by = blockIdx.y;

    for (int t = tid; t < 4096; t += 256) {
        int row = t >> 5, c4 = (t & 31) << 2;
        float4 v = make_float4(0.f, 0.f, 0.f, 0.f);
        int m = m0 + row;
        if (m < N_NODES) v = *(const float4*)&x[(size_t)m * 128 + c4];
        *(float4*)&As[row * GM_LDA + c4] = v;
    }
    const float* Bsrc = (by < 4) ? (W + (size_t)by * 64 * 128) : resW;
    for (int t = tid; t < 2048; t += 256) {
        int row = t >> 5, c4 = (t & 31) << 2;
        *(float4*)&Bs[row * GM_LDA + c4] = *(const float4*)&Bsrc[(size_t)row * 128 + c4];
    }
    __syncthreads();

    float acc[4][2][4];
    #pragma unroll
    for (int i = 0; i < 4; i++)
        #pragma unroll
        for (int j = 0; j < 2; j++)
            #pragma unroll
            for (int q = 0; q < 4; q++) acc[i][j][q] = 0.f;

    int g = lane >> 2, t4 = lane & 3;
    const float* arow = &As[(warp_m * 64 + g) * GM_LDA];
    const float* brow = &Bs[(warp_n * 16 + g) * GM_LDA];
    const uint32_t HM = 0xFFFFE000u;

    #pragma unroll 4
    for (int ks = 0; ks < 16; ks++) {
        int k0 = ks * 8;
        uint32_t ahi[4][4], alo[4][4];
        #pragma unroll
        for (int fm = 0; fm < 4; fm++) {
            const float* p = arow + fm * 16 * GM_LDA + k0 + t4;
            float v0 = p[0], v1 = p[8 * GM_LDA], v2 = p[4], v3 = p[8 * GM_LDA + 4];
            ahi[fm][0] = __float_as_uint(v0) & HM;
            ahi[fm][1] = __float_as_uint(v1) & HM;
            ahi[fm][2] = __float_as_uint(v2) & HM;
            ahi[fm][3] = __float_as_uint(v3) & HM;
            alo[fm][0] = __float_as_uint(v0 - __uint_as_float(ahi[fm][0]));
            alo[fm][1] = __float_as_uint(v1 - __uint_as_float(ahi[fm][1]));
            alo[fm][2] = __float_as_uint(v2 - __uint_as_float(ahi[fm][2]));
            alo[fm][3] = __float_as_uint(v3 - __uint_as_float(ahi[fm][3]));
        }
        uint32_t bhi[2][2], blo[2][2];
        #pragma unroll
        for (int fn = 0; fn < 2; fn++) {
            const float* p = brow + fn * 8 * GM_LDA + k0 + t4;
            float v0 = p[0], v1 = p[4];
            bhi[fn][0] = __float_as_uint(v0) & HM;
            bhi[fn][1] = __float_as_uint(v1) & HM;
            blo[fn][0] = __float_as_uint(v0 - __uint_as_float(bhi[fn][0]));
            blo[fn][1] = __float_as_uint(v1 - __uint_as_float(bhi[fn][1]));
        }
        #pragma unroll
        for (int fm = 0; fm < 4; fm++)
            #pragma unroll
            for (int fn = 0; fn < 2; fn++) {
                MMA_TF32(acc[fm][fn], alo[fm], bhi[fn]);
                MMA_TF32(acc[fm][fn], ahi[fm], blo[fn]);
                MMA_TF32(acc[fm][fn], ahi[fm], bhi[fn]);
            }
    }
    __syncthreads();

    float* s_as = As;
    float* s_ad = As + 128;
    if (by < 4) {
        if (tid < 128) { s_as[tid] = 0.f; s_ad[tid] = 0.f; }
        __syncthreads();
    }
    int cbase = warp_n * 16 + t4 * 2;
    #pragma unroll
    for (int fm = 0; fm < 4; fm++) {
        #pragma unroll
        for (int rs = 0; rs < 2; rs++) {
            int rloc = warp_m * 64 + fm * 16 + g + rs * 8;
            int m = m0 + rloc;
            bool ok = (m < N_NODES);
            float ps = 0.f, pd = 0.f;
            #pragma unroll
            for (int fn = 0; fn < 2; fn++) {
                float v0 = acc[fm][fn][rs * 2 + 0];
                float v1 = acc[fm][fn][rs * 2 + 1];
                int cl = cbase + fn * 8;
                if (ok) {
                    if (by < 4) {
                        g_xl[(size_t)m * 256 + by * 64 + cl]     = v0;
                        g_xl[(size_t)m * 256 + by * 64 + cl + 1] = v1;
                    } else {
                        g_resid[(size_t)m * 64 + cl]     = v0;
                        g_resid[(size_t)m * 64 + cl + 1] = v1;
                    }
                }
                if (by < 4) {
                    ps += v0 * att_src[by * 64 + cl] + v1 * att_src[by * 64 + cl + 1];
                    pd += v0 * att_dst[by * 64 + cl] + v1 * att_dst[by * 64 + cl + 1];
                }
            }
            if (by < 4) { atomicAdd(&s_as[rloc], ps); atomicAdd(&s_ad[rloc], pd); }
        }
    }
    if (by < 4) {
        __syncthreads();
        if (tid < 128) {
            int m = m0 + tid;
            if (m < N_NODES) {
                g_asrc[m * 4 + by] = s_as[tid];
                g_adst[m * 4 + by] = s_ad[tid];
            }
        }
    }
}

// -------------------- 3: CSR build: count, scan, fill ------------------------
__global__ void __launch_bounds__(256) k_count(const void* __restrict__ ei) {
    int e = blockIdx.x * blockDim.x + threadIdx.x;
    if (e >= E_EDGES) return;
    int d = load_idx(ei, (long long)E_EDGES + e);
    atomicAdd(&g_cnt[d], 1);
}

__global__ void __launch_bounds__(256) k_scan1() {
    __shared__ int sh[256];
    int i = blockIdx.x * 256 + threadIdx.x;
    sh[threadIdx.x] = (i < N_NODES) ? g_cnt[i] : 0;
    __syncthreads();
    for (int s = 128; s > 0; s >>= 1) {
        if (threadIdx.x < s) sh[threadIdx.x] += sh[threadIdx.x + s];
        __syncthreads();
    }
    if (threadIdx.x == 0) g_bsum[blockIdx.x] = sh[0];
}

__global__ void __launch_bounds__(512) k_scan2() {
    __shared__ int sh[512];
    int t = threadIdx.x;
    int v = (t < NBLK) ? g_bsum[t] : 0;
    sh[t] = v;
    __syncthreads();
    // Hillis-Steele inclusive scan
    for (int s = 1; s < 512; s <<= 1) {
        int add = (t >= s) ? sh[t - s] : 0;
        __syncthreads();
        sh[t] += add;
        __syncthreads();
    }
    if (t < NBLK) g_bsum[t] = sh[t] - v;   // exclusive
    if (t == 0) g_off[N_NODES] = E_EDGES;
}

__global__ void __launch_bounds__(256) k_scan3() {
    __shared__ int sh[256];
    int i = blockIdx.x * 256 + threadIdx.x;
    int t = threadIdx.x;
    int v = (i < N_NODES) ? g_cnt[i] : 0;
    sh[t] = v;
    __syncthreads();
    for (int s = 1; s < 256; s <<= 1) {
        int add = (t >= s) ? sh[t - s] : 0;
        __syncthreads();
        sh[t] += add;
        __syncthreads();
    }
    if (i < N_NODES) {
        int off = g_bsum[blockIdx.x] + sh[t] - v;
        g_off[i] = off;
        g_pos[i] = off;
    }
}

__global__ void __launch_bounds__(256) k_fill(const void* __restrict__ ei) {
    int e = blockIdx.x * blockDim.x + threadIdx.x;
    if (e >= E_EDGES) return;
    int s = load_idx(ei, e);
    int d = load_idx(ei, (long long)E_EDGES + e);
    int p = atomicAdd(&g_pos[d], 1);
    g_srcs[p] = s;
}

// -------------------- 4: CSR aggregation (warp per dst node) -----------------
// Single pass: denom and numerator together; softmax shift-invariant (no max).
// Fuses head-mean, GAT bias, residual. No float atomics.
__global__ void __launch_bounds__(256) k_agg_csr(const float* __restrict__ bias_gat,
                                                 const float* __restrict__ res_b) {
    int n = (blockIdx.x * blockDim.x + threadIdx.x) >> 5;
    int lane = threadIdx.x & 31;
    if (n >= N_NODES) return;

    float4 ad = *(const float4*)&g_adst[n * 4];
    // accumulators: per head, 2 channels (c0 = 2*lane, c1 = 2*lane+1)
    float a00 = 0.f, a01 = 0.f, a10 = 0.f, a11 = 0.f;
    float a20 = 0.f, a21 = 0.f, a30 = 0.f, a31 = 0.f;
    float d0 = 0.f, d1 = 0.f, d2 = 0.f, d3 = 0.f;
    int c0 = lane * 2;

    // self loop
    {
        float4 as = *(const float4*)&g_asrc[n * 4];
        float t0 = as.x + ad.x; t0 = t0 > 0.f ? t0 : NEG_SLOPE * t0;
        float t1 = as.y + ad.y; t1 = t1 > 0.f ? t1 : NEG_SLOPE * t1;
        float t2 = as.z + ad.z; t2 = t2 > 0.f ? t2 : NEG_SLOPE * t2;
        float t3 = as.w + ad.w; t3 = t3 > 0.f ? t3 : NEG_SLOPE * t3;
        float e0 = expf(t0), e1 = expf(t1), e2 = expf(t2), e3 = expf(t3);
        const float* xr = &g_xl[(size_t)n * 256];
        float2 v0 = *(const float2*)&xr[c0];
        float2 v1 = *(const float2*)&xr[64 + c0];
        float2 v2 = *(const float2*)&xr[128 + c0];
        float2 v3 = *(const float2*)&xr[192 + c0];
        a00 += e0 * v0.x; a01 += e0 * v0.y;
        a10 += e1 * v1.x; a11 += e1 * v1.y;
        a20 += e2 * v2.x; a21 += e2 * v2.y;
        a30 += e3 * v3.x; a31 += e3 * v3.y;
        d0 += e0; d1 += e1; d2 += e2; d3 += e3;
    }

    int beg = g_off[n], end = g_off[n + 1];
    for (int base = beg; base < end; base += 32) {
        int idx = base + lane;
        int s = 0;
        float e0 = 0.f, e1 = 0.f, e2 = 0.f, e3 = 0.f;
        if (idx < end) {
            s = g_srcs[idx];
            float4 as = *(const float4*)&g_asrc[s * 4];
            float t0 = as.x + ad.x; t0 = t0 > 0.f ? t0 : NEG_SLOPE * t0;
            float t1 = as.y + ad.y; t1 = t1 > 0.f ? t1 : NEG_SLOPE * t1;
            float t2 = as.z + ad.z; t2 = t2 > 0.f ? t2 : NEG_SLOPE * t2;
            float t3 = as.w + ad.w; t3 = t3 > 0.f ? t3 : NEG_SLOPE * t3;
            e0 = expf(t0); e1 = expf(t1); e2 = expf(t2); e3 = expf(t3);
        }
        int cnt = end - base; if (cnt > 32) cnt = 32;
        if (cnt == 32) {
            #pragma unroll 4
            for (int j = 0; j < 32; j++) {
                int sj = __shfl_sync(0xffffffffu, s, j);
                float f0 = __shfl_sync(0xffffffffu, e0, j);
                float f1 = __shfl_sync(0xffffffffu, e1, j);
                float f2 = __shfl_sync(0xffffffffu, e2, j);
                float f3 = __shfl_sync(0xffffffffu, e3, j);
                const float* xr = &g_xl[(size_t)sj * 256];
                float2 v0 = *(const float2*)&xr[c0];
                float2 v1 = *(const float2*)&xr[64 + c0];
                float2 v2 = *(const float2*)&xr[128 + c0];
                float2 v3 = *(const float2*)&xr[192 + c0];
                a00 += f0 * v0.x; a01 += f0 * v0.y;
                a10 += f1 * v1.x; a11 += f1 * v1.y;
                a20 += f2 * v2.x; a21 += f2 * v2.y;
                a30 += f3 * v3.x; a31 += f3 * v3.y;
                d0 += f0; d1 += f1; d2 += f2; d3 += f3;
            }
        } else {
            for (int j = 0; j < cnt; j++) {
                int sj = __shfl_sync(0xffffffffu, s, j);
                float f0 = __shfl_sync(0xffffffffu, e0, j);
                float f1 = __shfl_sync(0xffffffffu, e1, j);
                float f2 = __shfl_sync(0xffffffffu, e2, j);
                float f3 = __shfl_sync(0xffffffffu, e3, j);
                const float* xr = &g_xl[(size_t)sj * 256];
                float2 v0 = *(const float2*)&xr[c0];
                float2 v1 = *(const float2*)&xr[64 + c0];
                float2 v2 = *(const float2*)&xr[128 + c0];
                float2 v3 = *(const float2*)&xr[192 + c0];
                a00 += f0 * v0.x; a01 += f0 * v0.y;
                a10 += f1 * v1.x; a11 += f1 * v1.y;
                a20 += f2 * v2.x; a21 += f2 * v2.y;
                a30 += f3 * v3.x; a31 += f3 * v3.y;
                d0 += f0; d1 += f1; d2 += f2; d3 += f3;
            }
        }
    }

    float r0 = 0.25f * (a00 / d0 + a10 / d1 + a20 / d2 + a30 / d3);
    float r1 = 0.25f * (a01 / d0 + a11 / d1 + a21 / d2 + a31 / d3);
    float2 rb = *(const float2*)&g_resid[(size_t)n * 64 + c0];
    r0 += bias_gat[c0]     + res_b[c0]     + rb.x;
    r1 += bias_gat[c0 + 1] + res_b[c0 + 1] + rb.y;
    *(float2*)&g_acc[(size_t)n * 64 + c0] = make_float2(r0, r1);
}

// -------------------- 5: batch segment boundaries ----------------------------
__global__ void __launch_bounds__(256) k_bounds(const void* __restrict__ batch) {
    int n = blockIdx.x * blockDim.x + threadIdx.x;
    if (n >= N_NODES) return;
    int bn = load_idx(batch, n);
    if (n == 0) {
        for (int b = 0; b <= bn; b++) g_start[b] = 0;
    } else {
        int pb = load_idx(batch, n - 1);
        for (int b = pb + 1; b <= bn; b++) g_start[b] = n;
    }
    if (n == N_NODES - 1)
        for (int b = bn + 1; b <= B_GRAPHS; b++) g_start[b] = N_NODES;
}

// -------------------- 6: per-graph per-channel stats --------------------------
__global__ void __launch_bounds__(512) k_stats(const float* __restrict__ gn_mean_scale) {
    int b = blockIdx.x;
    int t = threadIdx.x;
    int c = t & 63, g = t >> 6;
    int s0 = g_start[b], s1 = g_start[b + 1];
    float sum = 0.f, sq = 0.f;
    for (int n = s0 + g; n < s1; n += 8) {
        float v = g_acc[(size_t)n * 64 + c];
        sum += v; sq += v * v;
    }
    __shared__ float sh[512], sh2[512];
    sh[t] = sum; sh2[t] = sq;
    __syncthreads();
    if (g == 0) {
        #pragma unroll
        for (int k = 1; k < 8; k++) { sum += sh[k * 64 + c]; sq += sh2[k * 64 + c]; }
        float cnt = (float)(s1 - s0);
        if (cnt > 0.f) {
            float mean = sum / cnt;
            float ms = mean * gn_mean_scale[c];
            float var = sq / cnt - 2.f * ms * mean + ms * ms;
            g_ms[b * 64 + c] = ms;
            g_inv[b * 64 + c] = rsqrtf(var + EPS_GN);
        }
    }
}

// -------------------- 7: normalize + tanh-GELU -------------------------------
__global__ void __launch_bounds__(256) k_norm(const void* __restrict__ batch,
                                              const float* __restrict__ gn_w,
                                              const float* __restrict__ gn_b,
                                              float* __restrict__ out) {
    int i = blockIdx.x * blockDim.x + threadIdx.x;
    if (i >= N_NODES * 64) return;
    int n = i >> 6, c = i & 63;
    int b = load_idx(batch, n);
    float cent = g_acc[i] - g_ms[b * 64 + c];
    float y = gn_w[c] * cent * g_inv[b * 64 + c] + gn_b[c];
    float t = tanhf(0.7978845608028654f * (y + 0.044715f * y * y * y));
    out[i] = 0.5f * y * (1.f + t);
}

// -------------------- launch --------------------------------------------------
extern "C" void kernel_launch(void* const* d_in, const int* in_sizes, int n_in,
                              void* d_out, int out_size) {
    const float* x        = (const float*)d_in[0];
    const void*  ei       = d_in[1];
    const void*  batch    = d_in[2];
    const float* W        = (const float*)d_in[3];
    const float* att_src  = (const float*)d_in[4];
    const float* att_dst  = (const float*)d_in[5];
    const float* bias_gat = (const float*)d_in[6];
    const float* res_W    = (const float*)d_in[7];
    const float* res_b    = (const float*)d_in[8];
    const float* gn_w     = (const float*)d_in[9];
    const float* gn_b     = (const float*)d_in[10];
    const float* gn_msc   = (const float*)d_in[11];
    float* out = (float*)d_out;

    cudaFuncSetAttribute(k_gemm_mma, cudaFuncAttributeMaxDynamicSharedMemorySize, GM_SMEM);

    k_detect<<<1, 32>>>(ei);
    k_zero<<<NBLK, 256>>>();

    dim3 ggrid((N_NODES + 127) / 128, 5);
    k_gemm_mma<<<ggrid, 256, GM_SMEM>>>(x, W, res_W, att_src, att_dst);

    // CSR build (overlaps GEMM in the same stream order; independent of it)
    k_count<<<(E_EDGES + 255) / 256, 256>>>(ei);
    k_scan1<<<NBLK, 256>>>();
    k_scan2<<<1, 512>>>();
    k_scan3<<<NBLK, 256>>>();
    k_fill<<<(E_EDGES + 255) / 256, 256>>>(ei);

    k_agg_csr<<<(N_NODES * 32 + 255) / 256, 256>>>(bias_gat, res_b);

    k_bounds<<<(N_NODES + 255) / 256, 256>>>(batch);
    k_stats<<<B_GRAPHS, 512>>>(gn_msc);
    k_norm<<<(N_NODES * 64 + 255) / 256, 256>>>(batch, gn_w, gn_b, out);
}

// round 10
// speedup vs baseline: 1.1139x; 1.1139x over previous
#include <cuda_runtime.h>
#include <cuda_bf16.h>
#include <cstdint>

// Problem constants
#define N_NODES 100000
#define F_INPUT 128
#define E_EDGES 1200000
#define B_GRAPHS 8
#define NE      (E_EDGES + N_NODES)   // 1,300,000
#define NEG_SLOPE 0.2f
#define EPS_GN   1e-5f

// -------------------- scratch (static device globals; no allocs) ------------
__device__ float g_xl[N_NODES * 256];       // [N, H*C]
__device__ float g_resid[N_NODES * 64];     // x @ res_W^T
__device__ float g_asrc[N_NODES * 4];
__device__ float g_adst[N_NODES * 4];
__device__ float g_denom[N_NODES * 4];
__device__ float g_acc[N_NODES * 64];
__device__ int   g_start[B_GRAPHS + 1];
__device__ float g_ms[B_GRAPHS * 64];
__device__ float g_inv[B_GRAPHS * 64];
__device__ int   g_idx64;

// -------------------- generic helpers ---------------------------------------
__device__ __forceinline__ int load_idx(const void* p, long long i) {
    if (g_idx64) return (int)((const long long*)p)[i];
    return ((const int*)p)[i];
}

__device__ __forceinline__ void red_add_v4(float* p, float a, float b, float c, float d) {
    asm volatile("red.global.add.v4.f32 [%0], {%1, %2, %3, %4};"
                 :: "l"(p), "f"(a), "f"(b), "f"(c), "f"(d) : "memory");
}

// m16n8k16 bf16 mma (legacy tensor path; sm_80+ PTX, works on plain sm_103 target)
#define MMA_BF16(c, a, b) \
    asm volatile("mma.sync.aligned.m16n8k16.row.col.f32.bf16.bf16.f32 " \
        "{%0,%1,%2,%3}, {%4,%5,%6,%7}, {%8,%9}, {%0,%1,%2,%3};" \
        : "+f"((c)[0]), "+f"((c)[1]), "+f"((c)[2]), "+f"((c)[3]) \
        : "r"((a)[0]), "r"((a)[1]), "r"((a)[2]), "r"((a)[3]), \
          "r"((b)[0]), "r"((b)[1]))

// -------------------- 1: zero scratch + fused dtype detection ----------------
__global__ void k_init(const void* ei_raw) {
    int i = blockIdx.x * blockDim.x + threadIdx.x;
    int stride = gridDim.x * blockDim.x;
    for (int j = i; j < N_NODES * 64; j += stride) g_acc[j] = 0.f;
    for (int j = i; j < N_NODES * 4; j += stride) g_denom[j] = 0.f;
    if (i == 0) {
        const int* p = (const int*)ei_raw;
        int is64 = 1;
        #pragma unroll 1
        for (int q = 0; q < 64; q++)
            if (p[2 * q + 1] != 0) { is64 = 0; break; }
        g_idx64 = is64;
    }
}

// -------------------- 2: bf16-split mma GEMM + fused attn logits -------------
// CTA = 128 rows x 64 cols, full K=128 in SMEM as bf16 hi/lo tiles.
// grid.y 0..3 -> W heads, 4 -> res_W.
// C = Ahi*Bhi + Alo*Bhi + Ahi*Blo  (residual ~2^-17, far under 1e-3 gate).
#define LB 136                      // bf16 elements per row (128 + 8 pad)
#define GM_SMEM ((128 * LB * 2 + 64 * LB * 2) * 2)   // 104448 bytes

__device__ __forceinline__ uint32_t pack_bf2(__nv_bfloat16 a, __nv_bfloat16 b) {
    return ((uint32_t)__bfloat16_as_ushort(b) << 16) | __bfloat16_as_ushort(a);
}

__device__ __forceinline__ void bf16split4(float4 v, uint2& hi, uint2& lo) {
    __nv_bfloat16 h0 = __float2bfloat16_rn(v.x);
    __nv_bfloat16 h1 = __float2bfloat16_rn(v.y);
    __nv_bfloat16 h2 = __float2bfloat16_rn(v.z);
    __nv_bfloat16 h3 = __float2bfloat16_rn(v.w);
    __nv_bfloat16 l0 = __float2bfloat16_rn(v.x - __bfloat162float(h0));
    __nv_bfloat16 l1 = __float2bfloat16_rn(v.y - __bfloat162float(h1));
    __nv_bfloat16 l2 = __float2bfloat16_rn(v.z - __bfloat162float(h2));
    __nv_bfloat16 l3 = __float2bfloat16_rn(v.w - __bfloat162float(h3));
    hi.x = pack_bf2(h0, h1); hi.y = pack_bf2(h2, h3);
    lo.x = pack_bf2(l0, l1); lo.y = pack_bf2(l2, l3);
}

__global__ void __launch_bounds__(256, 2) k_gemm_mma(
    const float* __restrict__ x, const float* __restrict__ W,
    const float* __restrict__ resW,
    const float* __restrict__ att_src, const float* __restrict__ att_dst)
{
    extern __shared__ __align__(16) __nv_bfloat16 sm[];
    __nv_bfloat16* Ahi = sm;
    __nv_bfloat16* Alo = Ahi + 128 * LB;
    __nv_bfloat16* Bhi = Alo + 128 * LB;
    __nv_bfloat16* Blo = Bhi + 64 * LB;
    int tid = threadIdx.x, lane = tid & 31, wid = tid >> 5;
    int warp_m = wid >> 2, warp_n = wid & 3;   // 2 x 4 warps: 64x16 warp tiles
    int m0 = blockIdx.x * 128;
    int by = blockIdx.y;

    // Stage + split A (128x128) and B (64x128) once.
    for (int t = tid; t < 4096; t += 256) {
        int row = t >> 5, c4 = (t & 31) << 2;
        float4 v = make_float4(0.f, 0.f, 0.f, 0.f);
        int m = m0 + row;
        if (m < N_NODES) v = *(const float4*)&x[(size_t)m * 128 + c4];
        uint2 hi, lo; bf16split4(v, hi, lo);
        *(uint2*)&Ahi[row * LB + c4] = hi;
        *(uint2*)&Alo[row * LB + c4] = lo;
    }
    const float* Bsrc = (by < 4) ? (W + (size_t)by * 64 * 128) : resW;
    for (int t = tid; t < 2048; t += 256) {
        int row = t >> 5, c4 = (t & 31) << 2;
        float4 v = *(const float4*)&Bsrc[(size_t)row * 128 + c4];
        uint2 hi, lo; bf16split4(v, hi, lo);
        *(uint2*)&Bhi[row * LB + c4] = hi;
        *(uint2*)&Blo[row * LB + c4] = lo;
    }
    __syncthreads();

    float acc[4][2][4];
    #pragma unroll
    for (int i = 0; i < 4; i++)
        #pragma unroll
        for (int j = 0; j < 2; j++)
            #pragma unroll
            for (int q = 0; q < 4; q++) acc[i][j][q] = 0.f;

    int g = lane >> 2, t4 = lane & 3;

    #pragma unroll 2
    for (int kc = 0; kc < 8; kc++) {
        int kcol = kc * 16 + 2 * t4;
        uint32_t ah[4][4], al[4][4];
        #pragma unroll
        for (int fm = 0; fm < 4; fm++) {
            int base = (warp_m * 64 + fm * 16 + g) * LB + kcol;
            ah[fm][0] = *(const uint32_t*)&Ahi[base];
            ah[fm][1] = *(const uint32_t*)&Ahi[base + 8 * LB];
            ah[fm][2] = *(const uint32_t*)&Ahi[base + 8];
            ah[fm][3] = *(const uint32_t*)&Ahi[base + 8 * LB + 8];
            al[fm][0] = *(const uint32_t*)&Alo[base];
            al[fm][1] = *(const uint32_t*)&Alo[base + 8 * LB];
            al[fm][2] = *(const uint32_t*)&Alo[base + 8];
            al[fm][3] = *(const uint32_t*)&Alo[base + 8 * LB + 8];
        }
        uint32_t bh[2][2], bl[2][2];
        #pragma unroll
        for (int fn = 0; fn < 2; fn++) {
            int nb = (warp_n * 16 + fn * 8 + g) * LB + kcol;
            bh[fn][0] = *(const uint32_t*)&Bhi[nb];
            bh[fn][1] = *(const uint32_t*)&Bhi[nb + 8];
            bl[fn][0] = *(const uint32_t*)&Blo[nb];
            bl[fn][1] = *(const uint32_t*)&Blo[nb + 8];
        }
        #pragma unroll
        for (int fm = 0; fm < 4; fm++)
            #pragma unroll
            for (int fn = 0; fn < 2; fn++) {
                MMA_BF16(acc[fm][fn], al[fm], bh[fn]);
                MMA_BF16(acc[fm][fn], ah[fm], bl[fn]);
                MMA_BF16(acc[fm][fn], ah[fm], bh[fn]);
            }
    }
    __syncthreads();

    // Epilogue: store + fused per-head attention logits (smem reduce).
    float* s_as = (float*)sm;
    float* s_ad = s_as + 128;
    if (by < 4) {
        if (tid < 128) { s_as[tid] = 0.f; s_ad[tid] = 0.f; }
        __syncthreads();
    }
    int cbase = warp_n * 16 + t4 * 2;
    #pragma unroll
    for (int fm = 0; fm < 4; fm++) {
        #pragma unroll
        for (int rs = 0; rs < 2; rs++) {
            int rloc = warp_m * 64 + fm * 16 + g + rs * 8;
            int m = m0 + rloc;
            bool ok = (m < N_NODES);
            float ps = 0.f, pd = 0.f;
            #pragma unroll
            for (int fn = 0; fn < 2; fn++) {
                float v0 = acc[fm][fn][rs * 2 + 0];
                float v1 = acc[fm][fn][rs * 2 + 1];
                int cl = cbase + fn * 8;
                if (ok) {
                    if (by < 4) {
                        g_xl[(size_t)m * 256 + by * 64 + cl]     = v0;
                        g_xl[(size_t)m * 256 + by * 64 + cl + 1] = v1;
                    } else {
                        g_resid[(size_t)m * 64 + cl]     = v0;
                        g_resid[(size_t)m * 64 + cl + 1] = v1;
                    }
                }
                if (by < 4) {
                    ps += v0 * att_src[by * 64 + cl] + v1 * att_src[by * 64 + cl + 1];
                    pd += v0 * att_dst[by * 64 + cl] + v1 * att_dst[by * 64 + cl + 1];
                }
            }
            if (by < 4) { atomicAdd(&s_as[rloc], ps); atomicAdd(&s_ad[rloc], pd); }
        }
    }
    if (by < 4) {
        __syncthreads();
        if (tid < 128) {
            int m = m0 + tid;
            if (m < N_NODES) {
                g_asrc[m * 4 + by] = s_as[tid];
                g_adst[m * 4 + by] = s_ad[tid];
            }
        }
    }
}

// -------------------- 3: edge pass A: exp + segment-sum denominator ----------
// Softmax shift-invariant; logits are O(10), exp can't overflow -> no max pass.
__global__ void __launch_bounds__(256) k_edge_exp(const void* __restrict__ ei) {
    int e = blockIdx.x * blockDim.x + threadIdx.x;
    if (e >= NE) return;
    int s, d;
    if (e < E_EDGES) { s = load_idx(ei, e); d = load_idx(ei, (long long)E_EDGES + e); }
    else             { s = d = e - E_EDGES; }
    float4 as = *(const float4*)&g_asrc[s * 4];
    float4 ad = *(const float4*)&g_adst[d * 4];
    float a0 = as.x + ad.x; a0 = a0 > 0.f ? a0 : NEG_SLOPE * a0;
    float a1 = as.y + ad.y; a1 = a1 > 0.f ? a1 : NEG_SLOPE * a1;
    float a2 = as.z + ad.z; a2 = a2 > 0.f ? a2 : NEG_SLOPE * a2;
    float a3 = as.w + ad.w; a3 = a3 > 0.f ? a3 : NEG_SLOPE * a3;
    red_add_v4(&g_denom[d * 4], expf(a0), expf(a1), expf(a2), expf(a3));
}

// -------------------- 4: edge pass B: gather + head-folded scatter -----------
// (launch #4 -> gets the ncu capture this round)
// Half-warp per edge; lane ln handles channels 4*ln..4*ln+3; one v4 red each.
__global__ void __launch_bounds__(256) k_edge_agg(const void* __restrict__ ei) {
    long long gw = ((long long)blockIdx.x * 256 + threadIdx.x) >> 5;
    int lane = threadIdx.x & 31;
    long long e = gw * 2 + (lane >> 4);
    if (e >= NE) return;
    int ln = lane & 15;
    int s, d;
    if (e < E_EDGES) { s = load_idx(ei, e); d = load_idx(ei, E_EDGES + e); }
    else             { s = d = (int)(e - E_EDGES); }
    float4 as = *(const float4*)&g_asrc[s * 4];
    float4 ad = *(const float4*)&g_adst[d * 4];
    float a0 = as.x + ad.x; a0 = a0 > 0.f ? a0 : NEG_SLOPE * a0;
    float a1 = as.y + ad.y; a1 = a1 > 0.f ? a1 : NEG_SLOPE * a1;
    float a2 = as.z + ad.z; a2 = a2 > 0.f ? a2 : NEG_SLOPE * a2;
    float a3 = as.w + ad.w; a3 = a3 > 0.f ? a3 : NEG_SLOPE * a3;
    float4 dn = *(const float4*)&g_denom[d * 4];
    float c0 = expf(a0) / dn.x, c1 = expf(a1) / dn.y;
    float c2 = expf(a2) / dn.z, c3 = expf(a3) / dn.w;
    const float4* xr = (const float4*)&g_xl[(size_t)s * 256];
    float4 v0 = xr[ln], v1 = xr[16 + ln], v2 = xr[32 + ln], v3 = xr[48 + ln];
    red_add_v4(&g_acc[(size_t)d * 64 + ln * 4],
               c0 * v0.x + c1 * v1.x + c2 * v2.x + c3 * v3.x,
               c0 * v0.y + c1 * v1.y + c2 * v2.y + c3 * v3.y,
               c0 * v0.z + c1 * v1.z + c2 * v2.z + c3 * v3.z,
               c0 * v0.w + c1 * v1.w + c2 * v2.w + c3 * v3.w);
}

// -------------------- 5: h = acc/H + bias_gat + residual + res_b -------------
__global__ void __launch_bounds__(256) k_hcompute(const float* __restrict__ bias_gat,
                                                  const float* __restrict__ res_b) {
    int i = blockIdx.x * blockDim.x + threadIdx.x;
    if (i >= N_NODES * 64) return;
    int c = i & 63;
    g_acc[i] = g_acc[i] * 0.25f + bias_gat[c] + g_resid[i] + res_b[c];
}

// -------------------- 6: batch segment boundaries ----------------------------
__global__ void __launch_bounds__(256) k_bounds(const void* __restrict__ batch) {
    int n = blockIdx.x * blockDim.x + threadIdx.x;
    if (n >= N_NODES) return;
    int bn = load_idx(batch, n);
    if (n == 0) {
        for (int b = 0; b <= bn; b++) g_start[b] = 0;
    } else {
        int pb = load_idx(batch, n - 1);
        for (int b = pb + 1; b <= bn; b++) g_start[b] = n;
    }
    if (n == N_NODES - 1)
        for (int b = bn + 1; b <= B_GRAPHS; b++) g_start[b] = N_NODES;
}

// -------------------- 7: per-graph per-channel stats --------------------------
__global__ void __launch_bounds__(512) k_stats(const float* __restrict__ gn_mean_scale) {
    int b = blockIdx.x;
    int t = threadIdx.x;
    int c = t & 63, g = t >> 6;
    int s0 = g_start[b], s1 = g_start[b + 1];
    float sum = 0.f, sq = 0.f;
    for (int n = s0 + g; n < s1; n += 8) {
        float v = g_acc[(size_t)n * 64 + c];
        sum += v; sq += v * v;
    }
    __shared__ float sh[512], sh2[512];
    sh[t] = sum; sh2[t] = sq;
    __syncthreads();
    if (g == 0) {
        #pragma unroll
        for (int k = 1; k < 8; k++) { sum += sh[k * 64 + c]; sq += sh2[k * 64 + c]; }
        float cnt = (float)(s1 - s0);
        if (cnt > 0.f) {
            float mean = sum / cnt;
            float ms = mean * gn_mean_scale[c];
            float var = sq / cnt - 2.f * ms * mean + ms * ms;
            g_ms[b * 64 + c] = ms;
            g_inv[b * 64 + c] = rsqrtf(var + EPS_GN);
        }
    }
}

// -------------------- 8: normalize + tanh-GELU -------------------------------
__global__ void __launch_bounds__(256) k_norm(const void* __restrict__ batch,
                                              const float* __restrict__ gn_w,
                                              const float* __restrict__ gn_b,
                                              float* __restrict__ out) {
    int i = blockIdx.x * blockDim.x + threadIdx.x;
    if (i >= N_NODES * 64) return;
    int n = i >> 6, c = i & 63;
    int b = load_idx(batch, n);
    float cent = g_acc[i] - g_ms[b * 64 + c];
    float y = gn_w[c] * cent * g_inv[b * 64 + c] + gn_b[c];
    float t = tanhf(0.7978845608028654f * (y + 0.044715f * y * y * y));
    out[i] = 0.5f * y * (1.f + t);
}

// -------------------- launch --------------------------------------------------
extern "C" void kernel_launch(void* const* d_in, const int* in_sizes, int n_in,
                              void* d_out, int out_size) {
    const float* x        = (const float*)d_in[0];
    const void*  ei       = d_in[1];
    const void*  batch    = d_in[2];
    const float* W        = (const float*)d_in[3];
    const float* att_src  = (const float*)d_in[4];
    const float* att_dst  = (const float*)d_in[5];
    const float* bias_gat = (const float*)d_in[6];
    const float* res_W    = (const float*)d_in[7];
    const float* res_b    = (const float*)d_in[8];
    const float* gn_w     = (const float*)d_in[9];
    const float* gn_b     = (const float*)d_in[10];
    const float* gn_msc   = (const float*)d_in[11];
    float* out = (float*)d_out;

    cudaFuncSetAttribute(k_gemm_mma, cudaFuncAttributeMaxDynamicSharedMemorySize, GM_SMEM);

    k_init<<<2048, 256>>>(ei);                                  // launch 1

    dim3 ggrid((N_NODES + 127) / 128, 5);
    k_gemm_mma<<<ggrid, 256, GM_SMEM>>>(x, W, res_W, att_src, att_dst);  // 2

    k_edge_exp<<<(NE + 255) / 256, 256>>>(ei);                  // 3
    k_edge_agg<<<(NE / 2 + 7) / 8, 256>>>(ei);                  // 4  <- profiled

    k_hcompute<<<(N_NODES * 64 + 255) / 256, 256>>>(bias_gat, res_b);
    k_bounds<<<(N_NODES + 255) / 256, 256>>>(batch);
    k_stats<<<B_GRAPHS, 512>>>(gn_msc);
    k_norm<<<(N_NODES * 64 + 255) / 256, 256>>>(batch, gn_w, gn_b, out);
}

// round 12
// speedup vs baseline: 1.1938x; 1.0717x over previous
#include <cuda_runtime.h>
#include <cuda_bf16.h>
#include <cstdint>

// Problem constants
#define N_NODES 100000
#define F_INPUT 128
#define E_EDGES 1200000
#define B_GRAPHS 8
#define NE      (E_EDGES + N_NODES)   // 1,300,000
#define NEG_SLOPE 0.2f
#define EPS_GN   1e-5f

// -------------------- scratch (static device globals; no allocs) ------------
__device__ __nv_bfloat16 g_xl[N_NODES * 256];   // [N, H*C] bf16 (51.2 MB)
__device__ float g_resid[N_NODES * 64];         // x @ res_W^T (fp32)
__device__ float g_asrc[N_NODES * 4];
__device__ float g_adst[N_NODES * 4];
__device__ float g_denom[N_NODES * 4];
__device__ float g_acc[N_NODES * 64];
__device__ int   g_start[B_GRAPHS + 1];
__device__ float g_ms[B_GRAPHS * 64];
__device__ float g_inv[B_GRAPHS * 64];
__device__ int   g_idx64;

// -------------------- generic helpers ---------------------------------------
__device__ __forceinline__ int load_idx(const void* p, long long i) {
    if (g_idx64) return (int)((const long long*)p)[i];
    return ((const int*)p)[i];
}

__device__ __forceinline__ void red_add_v4(float* p, float a, float b, float c, float d) {
    asm volatile("red.global.add.v4.f32 [%0], {%1, %2, %3, %4};"
                 :: "l"(p), "f"(a), "f"(b), "f"(c), "f"(d) : "memory");
}

// m16n8k16 bf16 mma (legacy tensor path; sm_80+ PTX, works on plain sm_103 target)
#define MMA_BF16(c, a, b) \
    asm volatile("mma.sync.aligned.m16n8k16.row.col.f32.bf16.bf16.f32 " \
        "{%0,%1,%2,%3}, {%4,%5,%6,%7}, {%8,%9}, {%0,%1,%2,%3};" \
        : "+f"((c)[0]), "+f"((c)[1]), "+f"((c)[2]), "+f"((c)[3]) \
        : "r"((a)[0]), "r"((a)[1]), "r"((a)[2]), "r"((a)[3]), \
          "r"((b)[0]), "r"((b)[1]))

// -------------------- 1a/1b/1c: init split across 3 launches -----------------
// (3 launches before the GEMM so k_gemm_mma is launch #4 -> gets ncu capture)
__global__ void k_init_a() {
    int i = blockIdx.x * blockDim.x + threadIdx.x;
    int stride = gridDim.x * blockDim.x;
    for (int j = i; j < N_NODES * 32; j += stride) g_acc[j] = 0.f;
}
__global__ void k_init_b() {
    int i = blockIdx.x * blockDim.x + threadIdx.x;
    int stride = gridDim.x * blockDim.x;
    for (int j = i; j < N_NODES * 32; j += stride) g_acc[N_NODES * 32 + j] = 0.f;
}
__global__ void k_init_c(const void* ei_raw) {
    int i = blockIdx.x * blockDim.x + threadIdx.x;
    int stride = gridDim.x * blockDim.x;
    for (int j = i; j < N_NODES * 4; j += stride) g_denom[j] = 0.f;
    if (i == 0) {
        const int* p = (const int*)ei_raw;
        int is64 = 1;
        #pragma unroll 1
        for (int q = 0; q < 64; q++)
            if (p[2 * q + 1] != 0) { is64 = 0; break; }
        g_idx64 = is64;
    }
}

// -------------------- 2: bf16-split mma GEMM + fused attn logits -------------
// CTA = 128 rows x 64 cols, full K=128 in SMEM as bf16 hi/lo tiles.
// grid.y 0..3 -> W heads, 4 -> res_W.
// C = Ahi*Bhi + Alo*Bhi + Ahi*Blo  (residual ~2^-17).
#define LB 136
#define GM_SMEM ((128 * LB * 2 + 64 * LB * 2) * 2)   // 104448 bytes

__device__ __forceinline__ uint32_t pack_bf2(__nv_bfloat16 a, __nv_bfloat16 b) {
    return ((uint32_t)__bfloat16_as_ushort(b) << 16) | __bfloat16_as_ushort(a);
}

__device__ __forceinline__ void bf16split4(float4 v, uint2& hi, uint2& lo) {
    __nv_bfloat16 h0 = __float2bfloat16_rn(v.x);
    __nv_bfloat16 h1 = __float2bfloat16_rn(v.y);
    __nv_bfloat16 h2 = __float2bfloat16_rn(v.z);
    __nv_bfloat16 h3 = __float2bfloat16_rn(v.w);
    __nv_bfloat16 l0 = __float2bfloat16_rn(v.x - __bfloat162float(h0));
    __nv_bfloat16 l1 = __float2bfloat16_rn(v.y - __bfloat162float(h1));
    __nv_bfloat16 l2 = __float2bfloat16_rn(v.z - __bfloat162float(h2));
    __nv_bfloat16 l3 = __float2bfloat16_rn(v.w - __bfloat162float(h3));
    hi.x = pack_bf2(h0, h1); hi.y = pack_bf2(h2, h3);
    lo.x = pack_bf2(l0, l1); lo.y = pack_bf2(l2, l3);
}

__global__ void __launch_bounds__(256, 2) k_gemm_mma(
    const float* __restrict__ x, const float* __restrict__ W,
    const float* __restrict__ resW,
    const float* __restrict__ att_src, const float* __restrict__ att_dst)
{
    extern __shared__ __align__(16) __nv_bfloat16 sm[];
    __nv_bfloat16* Ahi = sm;
    __nv_bfloat16* Alo = Ahi + 128 * LB;
    __nv_bfloat16* Bhi = Alo + 128 * LB;
    __nv_bfloat16* Blo = Bhi + 64 * LB;
    int tid = threadIdx.x, lane = tid & 31, wid = tid >> 5;
    int warp_m = wid >> 2, warp_n = wid & 3;
    int m0 = blockIdx.x * 128;
    int by = blockIdx.y;

    for (int t = tid; t < 4096; t += 256) {
        int row = t >> 5, c4 = (t & 31) << 2;
        float4 v = make_float4(0.f, 0.f, 0.f, 0.f);
        int m = m0 + row;
        if (m < N_NODES) v = *(const float4*)&x[(size_t)m * 128 + c4];
        uint2 hi, lo; bf16split4(v, hi, lo);
        *(uint2*)&Ahi[row * LB + c4] = hi;
        *(uint2*)&Alo[row * LB + c4] = lo;
    }
    const float* Bsrc = (by < 4) ? (W + (size_t)by * 64 * 128) : resW;
    for (int t = tid; t < 2048; t += 256) {
        int row = t >> 5, c4 = (t & 31) << 2;
        float4 v = *(const float4*)&Bsrc[(size_t)row * 128 + c4];
        uint2 hi, lo; bf16split4(v, hi, lo);
        *(uint2*)&Bhi[row * LB + c4] = hi;
        *(uint2*)&Blo[row * LB + c4] = lo;
    }
    __syncthreads();

    float acc[4][2][4];
    #pragma unroll
    for (int i = 0; i < 4; i++)
        #pragma unroll
        for (int j = 0; j < 2; j++)
            #pragma unroll
            for (int q = 0; q < 4; q++) acc[i][j][q] = 0.f;

    int g = lane >> 2, t4 = lane & 3;

    #pragma unroll 2
    for (int kc = 0; kc < 8; kc++) {
        int kcol = kc * 16 + 2 * t4;
        uint32_t ah[4][4], al[4][4];
        #pragma unroll
        for (int fm = 0; fm < 4; fm++) {
            int base = (warp_m * 64 + fm * 16 + g) * LB + kcol;
            ah[fm][0] = *(const uint32_t*)&Ahi[base];
            ah[fm][1] = *(const uint32_t*)&Ahi[base + 8 * LB];
            ah[fm][2] = *(const uint32_t*)&Ahi[base + 8];
            ah[fm][3] = *(const uint32_t*)&Ahi[base + 8 * LB + 8];
            al[fm][0] = *(const uint32_t*)&Alo[base];
            al[fm][1] = *(const uint32_t*)&Alo[base + 8 * LB];
            al[fm][2] = *(const uint32_t*)&Alo[base + 8];
            al[fm][3] = *(const uint32_t*)&Alo[base + 8 * LB + 8];
        }
        uint32_t bh[2][2], bl[2][2];
        #pragma unroll
        for (int fn = 0; fn < 2; fn++) {
            int nb = (warp_n * 16 + fn * 8 + g) * LB + kcol;
            bh[fn][0] = *(const uint32_t*)&Bhi[nb];
            bh[fn][1] = *(const uint32_t*)&Bhi[nb + 8];
            bl[fn][0] = *(const uint32_t*)&Blo[nb];
            bl[fn][1] = *(const uint32_t*)&Blo[nb + 8];
        }
        #pragma unroll
        for (int fm = 0; fm < 4; fm++)
            #pragma unroll
            for (int fn = 0; fn < 2; fn++) {
                MMA_BF16(acc[fm][fn], al[fm], bh[fn]);
                MMA_BF16(acc[fm][fn], ah[fm], bl[fn]);
                MMA_BF16(acc[fm][fn], ah[fm], bh[fn]);
            }
    }
    __syncthreads();

    // Epilogue: bf16-packed xl stores (heads) / fp32 resid + fused attn logits.
    float* s_as = (float*)sm;
    float* s_ad = s_as + 128;
    if (by < 4) {
        if (tid < 128) { s_as[tid] = 0.f; s_ad[tid] = 0.f; }
        __syncthreads();
    }
    int cbase = warp_n * 16 + t4 * 2;
    #pragma unroll
    for (int fm = 0; fm < 4; fm++) {
        #pragma unroll
        for (int rs = 0; rs < 2; rs++) {
            int rloc = warp_m * 64 + fm * 16 + g + rs * 8;
            int m = m0 + rloc;
            bool ok = (m < N_NODES);
            float ps = 0.f, pd = 0.f;
            #pragma unroll
            for (int fn = 0; fn < 2; fn++) {
                float v0 = acc[fm][fn][rs * 2 + 0];
                float v1 = acc[fm][fn][rs * 2 + 1];
                int cl = cbase + fn * 8;
                if (ok) {
                    if (by < 4) {
                        uint32_t pk = pack_bf2(__float2bfloat16_rn(v0),
                                               __float2bfloat16_rn(v1));
                        *(uint32_t*)&g_xl[(size_t)m * 256 + by * 64 + cl] = pk;
                    } else {
                        g_resid[(size_t)m * 64 + cl]     = v0;
                        g_resid[(size_t)m * 64 + cl + 1] = v1;
                    }
                }
                if (by < 4) {
                    ps += v0 * att_src[by * 64 + cl] + v1 * att_src[by * 64 + cl + 1];
                    pd += v0 * att_dst[by * 64 + cl] + v1 * att_dst[by * 64 + cl + 1];
                }
            }
            if (by < 4) { atomicAdd(&s_as[rloc], ps); atomicAdd(&s_ad[rloc], pd); }
        }
    }
    if (by < 4) {
        __syncthreads();
        if (tid < 128) {
            int m = m0 + tid;
            if (m < N_NODES) {
                g_asrc[m * 4 + by] = s_as[tid];
                g_adst[m * 4 + by] = s_ad[tid];
            }
        }
    }
}

// -------------------- 3: edge pass A: exp + segment-sum denominator ----------
__global__ void __launch_bounds__(256) k_edge_exp(const void* __restrict__ ei) {
    int e = blockIdx.x * blockDim.x + threadIdx.x;
    if (e >= NE) return;
    int s, d;
    if (e < E_EDGES) { s = load_idx(ei, e); d = load_idx(ei, (long long)E_EDGES + e); }
    else             { s = d = e - E_EDGES; }
    float4 as = *(const float4*)&g_asrc[s * 4];
    float4 ad = *(const float4*)&g_adst[d * 4];
    float a0 = as.x + ad.x; a0 = a0 > 0.f ? a0 : NEG_SLOPE * a0;
    float a1 = as.y + ad.y; a1 = a1 > 0.f ? a1 : NEG_SLOPE * a1;
    float a2 = as.z + ad.z; a2 = a2 > 0.f ? a2 : NEG_SLOPE * a2;
    float a3 = as.w + ad.w; a3 = a3 > 0.f ? a3 : NEG_SLOPE * a3;
    red_add_v4(&g_denom[d * 4], expf(a0), expf(a1), expf(a2), expf(a3));
}

// -------------------- 4: edge pass B: bf16 gather + head-folded scatter ------
// Half-warp per edge; lane ln handles channels 4*ln..4*ln+3 (512B/edge gather).
__global__ void __launch_bounds__(256) k_edge_agg(const void* __restrict__ ei) {
    long long gw = ((long long)blockIdx.x * 256 + threadIdx.x) >> 5;
    int lane = threadIdx.x & 31;
    long long e = gw * 2 + (lane >> 4);
    if (e >= NE) return;
    int ln = lane & 15;
    int s, d;
    if (e < E_EDGES) { s = load_idx(ei, e); d = load_idx(ei, E_EDGES + e); }
    else             { s = d = (int)(e - E_EDGES); }
    float4 as = *(const float4*)&g_asrc[s * 4];
    float4 ad = *(const float4*)&g_adst[d * 4];
    float a0 = as.x + ad.x; a0 = a0 > 0.f ? a0 : NEG_SLOPE * a0;
    float a1 = as.y + ad.y; a1 = a1 > 0.f ? a1 : NEG_SLOPE * a1;
    float a2 = as.z + ad.z; a2 = a2 > 0.f ? a2 : NEG_SLOPE * a2;
    float a3 = as.w + ad.w; a3 = a3 > 0.f ? a3 : NEG_SLOPE * a3;
    float4 dn = *(const float4*)&g_denom[d * 4];
    float c0 = expf(a0) / dn.x, c1 = expf(a1) / dn.y;
    float c2 = expf(a2) / dn.z, c3 = expf(a3) / dn.w;
    const __nv_bfloat16* xr = &g_xl[(size_t)s * 256];
    uint2 u0 = *(const uint2*)&xr[ln * 4];
    uint2 u1 = *(const uint2*)&xr[64 + ln * 4];
    uint2 u2 = *(const uint2*)&xr[128 + ln * 4];
    uint2 u3 = *(const uint2*)&xr[192 + ln * 4];
    float2 p0a = __bfloat1622float2(*(const __nv_bfloat162*)&u0.x);
    float2 p0b = __bfloat1622float2(*(const __nv_bfloat162*)&u0.y);
    float2 p1a = __bfloat1622float2(*(const __nv_bfloat162*)&u1.x);
    float2 p1b = __bfloat1622float2(*(const __nv_bfloat162*)&u1.y);
    float2 p2a = __bfloat1622float2(*(const __nv_bfloat162*)&u2.x);
    float2 p2b = __bfloat1622float2(*(const __nv_bfloat162*)&u2.y);
    float2 p3a = __bfloat1622float2(*(const __nv_bfloat162*)&u3.x);
    float2 p3b = __bfloat1622float2(*(const __nv_bfloat162*)&u3.y);
    red_add_v4(&g_acc[(size_t)d * 64 + ln * 4],
               c0 * p0a.x + c1 * p1a.x + c2 * p2a.x + c3 * p3a.x,
               c0 * p0a.y + c1 * p1a.y + c2 * p2a.y + c3 * p3a.y,
               c0 * p0b.x + c1 * p1b.x + c2 * p2b.x + c3 * p3b.x,
               c0 * p0b.y + c1 * p1b.y + c2 * p2b.y + c3 * p3b.y);
}

// -------------------- 5: h = acc/H + bias_gat + residual + res_b -------------
__global__ void __launch_bounds__(256) k_hcompute(const float* __restrict__ bias_gat,
                                                  const float* __restrict__ res_b) {
    int i = blockIdx.x * blockDim.x + threadIdx.x;
    if (i >= N_NODES * 64) return;
    int c = i & 63;
    g_acc[i] = g_acc[i] * 0.25f + bias_gat[c] + g_resid[i] + res_b[c];
}

// -------------------- 6: batch segment boundaries ----------------------------
__global__ void __launch_bounds__(256) k_bounds(const void* __restrict__ batch) {
    int n = blockIdx.x * blockDim.x + threadIdx.x;
    if (n >= N_NODES) return;
    int bn = load_idx(batch, n);
    if (n == 0) {
        for (int b = 0; b <= bn; b++) g_start[b] = 0;
    } else {
        int pb = load_idx(batch, n - 1);
        for (int b = pb + 1; b <= bn; b++) g_start[b] = n;
    }
    if (n == N_NODES - 1)
        for (int b = bn + 1; b <= B_GRAPHS; b++) g_start[b] = N_NODES;
}

// -------------------- 7: per-graph per-channel stats --------------------------
__global__ void __launch_bounds__(512) k_stats(const float* __restrict__ gn_mean_scale) {
    int b = blockIdx.x;
    int t = threadIdx.x;
    int c = t & 63, g = t >> 6;
    int s0 = g_start[b], s1 = g_start[b + 1];
    float sum = 0.f, sq = 0.f;
    for (int n = s0 + g; n < s1; n += 8) {
        float v = g_acc[(size_t)n * 64 + c];
        sum += v; sq += v * v;
    }
    __shared__ float sh[512], sh2[512];
    sh[t] = sum; sh2[t] = sq;
    __syncthreads();
    if (g == 0) {
        #pragma unroll
        for (int k = 1; k < 8; k++) { sum += sh[k * 64 + c]; sq += sh2[k * 64 + c]; }
        float cnt = (float)(s1 - s0);
        if (cnt > 0.f) {
            float mean = sum / cnt;
            float ms = mean * gn_mean_scale[c];
            float var = sq / cnt - 2.f * ms * mean + ms * ms;
            g_ms[b * 64 + c] = ms;
            g_inv[b * 64 + c] = rsqrtf(var + EPS_GN);
        }
    }
}

// -------------------- 8: normalize + tanh-GELU -------------------------------
__global__ void __launch_bounds__(256) k_norm(const void* __restrict__ batch,
                                              const float* __restrict__ gn_w,
                                              const float* __restrict__ gn_b,
                                              float* __restrict__ out) {
    int i = blockIdx.x * blockDim.x + threadIdx.x;
    if (i >= N_NODES * 64) return;
    int n = i >> 6, c = i & 63;
    int b = load_idx(batch, n);
    float cent = g_acc[i] - g_ms[b * 64 + c];
    float y = gn_w[c] * cent * g_inv[b * 64 + c] + gn_b[c];
    float t = tanhf(0.7978845608028654f * (y + 0.044715f * y * y * y));
    out[i] = 0.5f * y * (1.f + t);
}

// -------------------- launch --------------------------------------------------
extern "C" void kernel_launch(void* const* d_in, const int* in_sizes, int n_in,
                              void* d_out, int out_size) {
    const float* x        = (const float*)d_in[0];
    const void*  ei       = d_in[1];
    const void*  batch    = d_in[2];
    const float* W        = (const float*)d_in[3];
    const float* att_src  = (const float*)d_in[4];
    const float* att_dst  = (const float*)d_in[5];
    const float* bias_gat = (const float*)d_in[6];
    const float* res_W    = (const float*)d_in[7];
    const float* res_b    = (const float*)d_in[8];
    const float* gn_w     = (const float*)d_in[9];
    const float* gn_b     = (const float*)d_in[10];
    const float* gn_msc   = (const float*)d_in[11];
    float* out = (float*)d_out;

    cudaFuncSetAttribute(k_gemm_mma, cudaFuncAttributeMaxDynamicSharedMemorySize, GM_SMEM);

    k_init_a<<<1024, 256>>>();                                  // 1
    k_init_b<<<1024, 256>>>();                                  // 2
    k_init_c<<<256, 256>>>(ei);                                 // 3

    dim3 ggrid((N_NODES + 127) / 128, 5);
    k_gemm_mma<<<ggrid, 256, GM_SMEM>>>(x, W, res_W, att_src, att_dst);  // 4 <- profiled

    k_edge_exp<<<(NE + 255) / 256, 256>>>(ei);
    k_edge_agg<<<(NE / 2 + 7) / 8, 256>>>(ei);

    k_hcompute<<<(N_NODES * 64 + 255) / 256, 256>>>(bias_gat, res_b);
    k_bounds<<<(N_NODES + 255) / 256, 256>>>(batch);
    k_stats<<<B_GRAPHS, 512>>>(gn_msc);
    k_norm<<<(N_NODES * 64 + 255) / 256, 256>>>(batch, gn_w, gn_b, out);
}

// round 13
// speedup vs baseline: 1.3786x; 1.1548x over previous
#include <cuda_runtime.h>
#include <cuda_bf16.h>
#include <cstdint>

// Problem constants
#define N_NODES 100000
#define F_INPUT 128
#define E_EDGES 1200000
#define B_GRAPHS 8
#define NE      (E_EDGES + N_NODES)   // 1,300,000
#define NEG_SLOPE 0.2f
#define EPS_GN   1e-5f

// -------------------- scratch (static device globals; no allocs) ------------
__device__ __nv_bfloat16 g_xl[N_NODES * 256];   // [N, H*C] bf16 (51.2 MB)
__device__ float g_resid[N_NODES * 64];         // x @ res_W^T (fp32)
__device__ float g_asrc[N_NODES * 4];
__device__ float g_adst[N_NODES * 4];
__device__ float g_denom[N_NODES * 4];
__device__ float g_acc[N_NODES * 64];
__device__ int   g_start[B_GRAPHS + 1];
__device__ float g_ms[B_GRAPHS * 64];
__device__ float g_inv[B_GRAPHS * 64];
__device__ int   g_idx64;

// -------------------- generic helpers ---------------------------------------
__device__ __forceinline__ int load_idx(const void* p, long long i) {
    if (g_idx64) return (int)((const long long*)p)[i];
    return ((const int*)p)[i];
}

__device__ __forceinline__ void red_add_v4(float* p, float a, float b, float c, float d) {
    asm volatile("red.global.add.v4.f32 [%0], {%1, %2, %3, %4};"
                 :: "l"(p), "f"(a), "f"(b), "f"(c), "f"(d) : "memory");
}

// m16n8k16 bf16 mma (legacy tensor path; sm_80+ PTX, works on plain sm_103 target)
#define MMA_BF16(c, a, b) \
    asm volatile("mma.sync.aligned.m16n8k16.row.col.f32.bf16.bf16.f32 " \
        "{%0,%1,%2,%3}, {%4,%5,%6,%7}, {%8,%9}, {%0,%1,%2,%3};" \
        : "+f"((c)[0]), "+f"((c)[1]), "+f"((c)[2]), "+f"((c)[3]) \
        : "r"((a)[0]), "r"((a)[1]), "r"((a)[2]), "r"((a)[3]), \
          "r"((b)[0]), "r"((b)[1]))

// -------------------- 1a/1b/1c: init split across 3 launches -----------------
// (3 launches before the GEMM so k_gemm_mma is launch #4 -> gets ncu capture)
__global__ void k_init_a() {
    int i = blockIdx.x * blockDim.x + threadIdx.x;
    int stride = gridDim.x * blockDim.x;
    for (int j = i; j < N_NODES * 32; j += stride) g_acc[j] = 0.f;
}
__global__ void k_init_b() {
    int i = blockIdx.x * blockDim.x + threadIdx.x;
    int stride = gridDim.x * blockDim.x;
    for (int j = i; j < N_NODES * 32; j += stride) g_acc[N_NODES * 32 + j] = 0.f;
}
__global__ void k_init_c(const void* ei_raw) {
    int i = blockIdx.x * blockDim.x + threadIdx.x;
    int stride = gridDim.x * blockDim.x;
    for (int j = i; j < N_NODES * 4; j += stride) g_denom[j] = 0.f;
    if (i == 0) {
        const int* p = (const int*)ei_raw;
        int is64 = 1;
        #pragma unroll 1
        for (int q = 0; q < 64; q++)
            if (p[2 * q + 1] != 0) { is64 = 0; break; }
        g_idx64 = is64;
    }
}

// -------------------- 2: bf16-split mma GEMM + fused attn logits -------------
// CTA = 128 rows x 64 cols, full K=128 in SMEM as bf16 hi/lo tiles.
// 512 threads, 4x4 warp grid, 32x16 warp tiles (2 CTAs/SM -> 32 warps/SM).
// grid.y 0..3 -> W heads, 4 -> res_W.
// C = Ahi*Bhi + Alo*Bhi + Ahi*Blo  (residual ~2^-17).
#define LB 136
#define GM_SMEM ((128 * LB * 2 + 64 * LB * 2) * 2)   // 104448 bytes

__device__ __forceinline__ uint32_t pack_bf2(__nv_bfloat16 a, __nv_bfloat16 b) {
    return ((uint32_t)__bfloat16_as_ushort(b) << 16) | __bfloat16_as_ushort(a);
}

__device__ __forceinline__ void bf16split4(float4 v, uint2& hi, uint2& lo) {
    __nv_bfloat16 h0 = __float2bfloat16_rn(v.x);
    __nv_bfloat16 h1 = __float2bfloat16_rn(v.y);
    __nv_bfloat16 h2 = __float2bfloat16_rn(v.z);
    __nv_bfloat16 h3 = __float2bfloat16_rn(v.w);
    __nv_bfloat16 l0 = __float2bfloat16_rn(v.x - __bfloat162float(h0));
    __nv_bfloat16 l1 = __float2bfloat16_rn(v.y - __bfloat162float(h1));
    __nv_bfloat16 l2 = __float2bfloat16_rn(v.z - __bfloat162float(h2));
    __nv_bfloat16 l3 = __float2bfloat16_rn(v.w - __bfloat162float(h3));
    hi.x = pack_bf2(h0, h1); hi.y = pack_bf2(h2, h3);
    lo.x = pack_bf2(l0, l1); lo.y = pack_bf2(l2, l3);
}

__global__ void __launch_bounds__(512, 2) k_gemm_mma(
    const float* __restrict__ x, const float* __restrict__ W,
    const float* __restrict__ resW,
    const float* __restrict__ att_src, const float* __restrict__ att_dst)
{
    extern __shared__ __align__(16) __nv_bfloat16 sm[];
    __nv_bfloat16* Ahi = sm;
    __nv_bfloat16* Alo = Ahi + 128 * LB;
    __nv_bfloat16* Bhi = Alo + 128 * LB;
    __nv_bfloat16* Blo = Bhi + 64 * LB;
    int tid = threadIdx.x, lane = tid & 31, wid = tid >> 5;
    int warp_m = wid >> 2, warp_n = wid & 3;   // 4x4 warps: 32x16 warp tiles
    int m0 = blockIdx.x * 128;
    int by = blockIdx.y;

    for (int t = tid; t < 4096; t += 512) {
        int row = t >> 5, c4 = (t & 31) << 2;
        float4 v = make_float4(0.f, 0.f, 0.f, 0.f);
        int m = m0 + row;
        if (m < N_NODES) v = *(const float4*)&x[(size_t)m * 128 + c4];
        uint2 hi, lo; bf16split4(v, hi, lo);
        *(uint2*)&Ahi[row * LB + c4] = hi;
        *(uint2*)&Alo[row * LB + c4] = lo;
    }
    const float* Bsrc = (by < 4) ? (W + (size_t)by * 64 * 128) : resW;
    for (int t = tid; t < 2048; t += 512) {
        int row = t >> 5, c4 = (t & 31) << 2;
        float4 v = *(const float4*)&Bsrc[(size_t)row * 128 + c4];
        uint2 hi, lo; bf16split4(v, hi, lo);
        *(uint2*)&Bhi[row * LB + c4] = hi;
        *(uint2*)&Blo[row * LB + c4] = lo;
    }
    __syncthreads();

    float acc[2][2][4];
    #pragma unroll
    for (int i = 0; i < 2; i++)
        #pragma unroll
        for (int j = 0; j < 2; j++)
            #pragma unroll
            for (int q = 0; q < 4; q++) acc[i][j][q] = 0.f;

    int g = lane >> 2, t4 = lane & 3;

    #pragma unroll 2
    for (int kc = 0; kc < 8; kc++) {
        int kcol = kc * 16 + 2 * t4;
        uint32_t ah[2][4], al[2][4];
        #pragma unroll
        for (int fm = 0; fm < 2; fm++) {
            int base = (warp_m * 32 + fm * 16 + g) * LB + kcol;
            ah[fm][0] = *(const uint32_t*)&Ahi[base];
            ah[fm][1] = *(const uint32_t*)&Ahi[base + 8 * LB];
            ah[fm][2] = *(const uint32_t*)&Ahi[base + 8];
            ah[fm][3] = *(const uint32_t*)&Ahi[base + 8 * LB + 8];
            al[fm][0] = *(const uint32_t*)&Alo[base];
            al[fm][1] = *(const uint32_t*)&Alo[base + 8 * LB];
            al[fm][2] = *(const uint32_t*)&Alo[base + 8];
            al[fm][3] = *(const uint32_t*)&Alo[base + 8 * LB + 8];
        }
        uint32_t bh[2][2], bl[2][2];
        #pragma unroll
        for (int fn = 0; fn < 2; fn++) {
            int nb = (warp_n * 16 + fn * 8 + g) * LB + kcol;
            bh[fn][0] = *(const uint32_t*)&Bhi[nb];
            bh[fn][1] = *(const uint32_t*)&Bhi[nb + 8];
            bl[fn][0] = *(const uint32_t*)&Blo[nb];
            bl[fn][1] = *(const uint32_t*)&Blo[nb + 8];
        }
        #pragma unroll
        for (int fm = 0; fm < 2; fm++)
            #pragma unroll
            for (int fn = 0; fn < 2; fn++) {
                MMA_BF16(acc[fm][fn], al[fm], bh[fn]);
                MMA_BF16(acc[fm][fn], ah[fm], bl[fn]);
                MMA_BF16(acc[fm][fn], ah[fm], bh[fn]);
            }
    }
    __syncthreads();

    // Epilogue: bf16-packed xl stores (heads) / fp32 resid + fused attn logits.
    float* s_as = (float*)sm;
    float* s_ad = s_as + 128;
    if (by < 4) {
        if (tid < 128) { s_as[tid] = 0.f; s_ad[tid] = 0.f; }
        __syncthreads();
    }
    int cbase = warp_n * 16 + t4 * 2;
    #pragma unroll
    for (int fm = 0; fm < 2; fm++) {
        #pragma unroll
        for (int rs = 0; rs < 2; rs++) {
            int rloc = warp_m * 32 + fm * 16 + g + rs * 8;
            int m = m0 + rloc;
            bool ok = (m < N_NODES);
            float ps = 0.f, pd = 0.f;
            #pragma unroll
            for (int fn = 0; fn < 2; fn++) {
                float v0 = acc[fm][fn][rs * 2 + 0];
                float v1 = acc[fm][fn][rs * 2 + 1];
                int cl = cbase + fn * 8;
                if (ok) {
                    if (by < 4) {
                        uint32_t pk = pack_bf2(__float2bfloat16_rn(v0),
                                               __float2bfloat16_rn(v1));
                        *(uint32_t*)&g_xl[(size_t)m * 256 + by * 64 + cl] = pk;
                    } else {
                        g_resid[(size_t)m * 64 + cl]     = v0;
                        g_resid[(size_t)m * 64 + cl + 1] = v1;
                    }
                }
                if (by < 4) {
                    ps += v0 * att_src[by * 64 + cl] + v1 * att_src[by * 64 + cl + 1];
                    pd += v0 * att_dst[by * 64 + cl] + v1 * att_dst[by * 64 + cl + 1];
                }
            }
            if (by < 4) { atomicAdd(&s_as[rloc], ps); atomicAdd(&s_ad[rloc], pd); }
        }
    }
    if (by < 4) {
        __syncthreads();
        if (tid < 128) {
            int m = m0 + tid;
            if (m < N_NODES) {
                g_asrc[m * 4 + by] = s_as[tid];
                g_adst[m * 4 + by] = s_ad[tid];
            }
        }
    }
}

// -------------------- 3: edge pass A: exp + segment-sum denominator ----------
__global__ void __launch_bounds__(256) k_edge_exp(const void* __restrict__ ei) {
    int e = blockIdx.x * blockDim.x + threadIdx.x;
    if (e >= NE) return;
    int s, d;
    if (e < E_EDGES) { s = load_idx(ei, e); d = load_idx(ei, (long long)E_EDGES + e); }
    else             { s = d = e - E_EDGES; }
    float4 as = *(const float4*)&g_asrc[s * 4];
    float4 ad = *(const float4*)&g_adst[d * 4];
    float a0 = as.x + ad.x; a0 = a0 > 0.f ? a0 : NEG_SLOPE * a0;
    float a1 = as.y + ad.y; a1 = a1 > 0.f ? a1 : NEG_SLOPE * a1;
    float a2 = as.z + ad.z; a2 = a2 > 0.f ? a2 : NEG_SLOPE * a2;
    float a3 = as.w + ad.w; a3 = a3 > 0.f ? a3 : NEG_SLOPE * a3;
    red_add_v4(&g_denom[d * 4], expf(a0), expf(a1), expf(a2), expf(a3));
}

// -------------------- 4: edge pass B: bf16 gather + head-folded scatter ------
// Half-warp per edge; lane ln handles channels 4*ln..4*ln+3 (512B/edge gather).
__global__ void __launch_bounds__(256) k_edge_agg(const void* __restrict__ ei) {
    long long gw = ((long long)blockIdx.x * 256 + threadIdx.x) >> 5;
    int lane = threadIdx.x & 31;
    long long e = gw * 2 + (lane >> 4);
    if (e >= NE) return;
    int ln = lane & 15;
    int s, d;
    if (e < E_EDGES) { s = load_idx(ei, e); d = load_idx(ei, E_EDGES + e); }
    else             { s = d = (int)(e - E_EDGES); }
    float4 as = *(const float4*)&g_asrc[s * 4];
    float4 ad = *(const float4*)&g_adst[d * 4];
    float a0 = as.x + ad.x; a0 = a0 > 0.f ? a0 : NEG_SLOPE * a0;
    float a1 = as.y + ad.y; a1 = a1 > 0.f ? a1 : NEG_SLOPE * a1;
    float a2 = as.z + ad.z; a2 = a2 > 0.f ? a2 : NEG_SLOPE * a2;
    float a3 = as.w + ad.w; a3 = a3 > 0.f ? a3 : NEG_SLOPE * a3;
    float4 dn = *(const float4*)&g_denom[d * 4];
    float c0 = expf(a0) / dn.x, c1 = expf(a1) / dn.y;
    float c2 = expf(a2) / dn.z, c3 = expf(a3) / dn.w;
    const __nv_bfloat16* xr = &g_xl[(size_t)s * 256];
    uint2 u0 = *(const uint2*)&xr[ln * 4];
    uint2 u1 = *(const uint2*)&xr[64 + ln * 4];
    uint2 u2 = *(const uint2*)&xr[128 + ln * 4];
    uint2 u3 = *(const uint2*)&xr[192 + ln * 4];
    float2 p0a = __bfloat1622float2(*(const __nv_bfloat162*)&u0.x);
    float2 p0b = __bfloat1622float2(*(const __nv_bfloat162*)&u0.y);
    float2 p1a = __bfloat1622float2(*(const __nv_bfloat162*)&u1.x);
    float2 p1b = __bfloat1622float2(*(const __nv_bfloat162*)&u1.y);
    float2 p2a = __bfloat1622float2(*(const __nv_bfloat162*)&u2.x);
    float2 p2b = __bfloat1622float2(*(const __nv_bfloat162*)&u2.y);
    float2 p3a = __bfloat1622float2(*(const __nv_bfloat162*)&u3.x);
    float2 p3b = __bfloat1622float2(*(const __nv_bfloat162*)&u3.y);
    red_add_v4(&g_acc[(size_t)d * 64 + ln * 4],
               c0 * p0a.x + c1 * p1a.x + c2 * p2a.x + c3 * p3a.x,
               c0 * p0a.y + c1 * p1a.y + c2 * p2a.y + c3 * p3a.y,
               c0 * p0b.x + c1 * p1b.x + c2 * p2b.x + c3 * p3b.x,
               c0 * p0b.y + c1 * p1b.y + c2 * p2b.y + c3 * p3b.y);
}

// -------------------- 5: h = acc/H + bias_gat + residual + res_b -------------
__global__ void __launch_bounds__(256) k_hcompute(const float* __restrict__ bias_gat,
                                                  const float* __restrict__ res_b) {
    int i = blockIdx.x * blockDim.x + threadIdx.x;
    if (i >= N_NODES * 64) return;
    int c = i & 63;
    g_acc[i] = g_acc[i] * 0.25f + bias_gat[c] + g_resid[i] + res_b[c];
}

// -------------------- 6: batch segment boundaries ----------------------------
__global__ void __launch_bounds__(256) k_bounds(const void* __restrict__ batch) {
    int n = blockIdx.x * blockDim.x + threadIdx.x;
    if (n >= N_NODES) return;
    int bn = load_idx(batch, n);
    if (n == 0) {
        for (int b = 0; b <= bn; b++) g_start[b] = 0;
    } else {
        int pb = load_idx(batch, n - 1);
        for (int b = pb + 1; b <= bn; b++) g_start[b] = n;
    }
    if (n == N_NODES - 1)
        for (int b = bn + 1; b <= B_GRAPHS; b++) g_start[b] = N_NODES;
}

// -------------------- 7: per-graph per-channel stats --------------------------
__global__ void __launch_bounds__(512) k_stats(const float* __restrict__ gn_mean_scale) {
    int b = blockIdx.x;
    int t = threadIdx.x;
    int c = t & 63, g = t >> 6;
    int s0 = g_start[b], s1 = g_start[b + 1];
    float sum = 0.f, sq = 0.f;
    for (int n = s0 + g; n < s1; n += 8) {
        float v = g_acc[(size_t)n * 64 + c];
        sum += v; sq += v * v;
    }
    __shared__ float sh[512], sh2[512];
    sh[t] = sum; sh2[t] = sq;
    __syncthreads();
    if (g == 0) {
        #pragma unroll
        for (int k = 1; k < 8; k++) { sum += sh[k * 64 + c]; sq += sh2[k * 64 + c]; }
        float cnt = (float)(s1 - s0);
        if (cnt > 0.f) {
            float mean = sum / cnt;
            float ms = mean * gn_mean_scale[c];
            float var = sq / cnt - 2.f * ms * mean + ms * ms;
            g_ms[b * 64 + c] = ms;
            g_inv[b * 64 + c] = rsqrtf(var + EPS_GN);
        }
    }
}

// -------------------- 8: normalize + tanh-GELU -------------------------------
__global__ void __launch_bounds__(256) k_norm(const void* __restrict__ batch,
                                              const float* __restrict__ gn_w,
                                              const float* __restrict__ gn_b,
                                              float* __restrict__ out) {
    int i = blockIdx.x * blockDim.x + threadIdx.x;
    if (i >= N_NODES * 64) return;
    int n = i >> 6, c = i & 63;
    int b = load_idx(batch, n);
    float cent = g_acc[i] - g_ms[b * 64 + c];
    float y = gn_w[c] * cent * g_inv[b * 64 + c] + gn_b[c];
    float t = tanhf(0.7978845608028654f * (y + 0.044715f * y * y * y));
    out[i] = 0.5f * y * (1.f + t);
}

// -------------------- launch --------------------------------------------------
extern "C" void kernel_launch(void* const* d_in, const int* in_sizes, int n_in,
                              void* d_out, int out_size) {
    const float* x        = (const float*)d_in[0];
    const void*  ei       = d_in[1];
    const void*  batch    = d_in[2];
    const float* W        = (const float*)d_in[3];
    const float* att_src  = (const float*)d_in[4];
    const float* att_dst  = (const float*)d_in[5];
    const float* bias_gat = (const float*)d_in[6];
    const float* res_W    = (const float*)d_in[7];
    const float* res_b    = (const float*)d_in[8];
    const float* gn_w     = (const float*)d_in[9];
    const float* gn_b     = (const float*)d_in[10];
    const float* gn_msc   = (const float*)d_in[11];
    float* out = (float*)d_out;

    cudaFuncSetAttribute(k_gemm_mma, cudaFuncAttributeMaxDynamicSharedMemorySize, GM_SMEM);

    k_init_a<<<1024, 256>>>();                                  // 1
    k_init_b<<<1024, 256>>>();                                  // 2
    k_init_c<<<256, 256>>>(ei);                                 // 3

    dim3 ggrid((N_NODES + 127) / 128, 5);
    k_gemm_mma<<<ggrid, 512, GM_SMEM>>>(x, W, res_W, att_src, att_dst);  // 4 <- profiled

    k_edge_exp<<<(NE + 255) / 256, 256>>>(ei);
    k_edge_agg<<<(NE / 2 + 7) / 8, 256>>>(ei);

    k_hcompute<<<(N_NODES * 64 + 255) / 256, 256>>>(bias_gat, res_b);
    k_bounds<<<(N_NODES + 255) / 256, 256>>>(batch);
    k_stats<<<B_GRAPHS, 512>>>(gn_msc);
    k_norm<<<(N_NODES * 64 + 255) / 256, 256>>>(batch, gn_w, gn_b, out);
}

// round 15
// speedup vs baseline: 1.3996x; 1.0152x over previous
#include <cuda_runtime.h>
#include <cuda_bf16.h>
#include <cstdint>

// Problem constants
#define N_NODES 100000
#define F_INPUT 128
#define E_EDGES 1200000
#define B_GRAPHS 8
#define NE      (E_EDGES + N_NODES)   // 1,300,000
#define NEG_SLOPE 0.2f
#define EPS_GN   1e-5f

// -------------------- scratch (static device globals; no allocs) ------------
__device__ __nv_bfloat16 g_xl[N_NODES * 256];   // [N, H*C] bf16 (51.2 MB)
__device__ float g_resid[N_NODES * 64];         // x @ res_W^T (fp32)
__device__ float g_asrc[N_NODES * 4];
__device__ float g_adst[N_NODES * 4];
__device__ float g_denom[N_NODES * 4];
__device__ float g_acc[N_NODES * 64];
__device__ int   g_start[B_GRAPHS + 1];
__device__ float g_ms[B_GRAPHS * 64];
__device__ float g_inv[B_GRAPHS * 64];
__device__ int   g_idx64;

// -------------------- generic helpers ---------------------------------------
__device__ __forceinline__ int load_idx(const void* p, long long i) {
    if (g_idx64) return (int)((const long long*)p)[i];
    return ((const int*)p)[i];
}

__device__ __forceinline__ void red_add_v4(float* p, float a, float b, float c, float d) {
    asm volatile("red.global.add.v4.f32 [%0], {%1, %2, %3, %4};"
                 :: "l"(p), "f"(a), "f"(b), "f"(c), "f"(d) : "memory");
}

__device__ __forceinline__ uint32_t smem_u32(const void* p) {
    uint32_t a;
    asm("{ .reg .u64 t; cvta.to.shared.u64 t, %1; cvt.u32.u64 %0, t; }" : "=r"(a) : "l"(p));
    return a;
}

// m16n8k16 bf16 mma (legacy tensor path; sm_80+ PTX)
#define MMA_BF16(c, a, b) \
    asm volatile("mma.sync.aligned.m16n8k16.row.col.f32.bf16.bf16.f32 " \
        "{%0,%1,%2,%3}, {%4,%5,%6,%7}, {%8,%9}, {%0,%1,%2,%3};" \
        : "+f"((c)[0]), "+f"((c)[1]), "+f"((c)[2]), "+f"((c)[3]) \
        : "r"((a)[0]), "r"((a)[1]), "r"((a)[2]), "r"((a)[3]), \
          "r"((b)[0]), "r"((b)[1]))

// ldmatrix 4x 8x8 b16 tiles (sm_75+)
#define LDSM_X4(r, addr) \
    asm volatile("ldmatrix.sync.aligned.m8n8.x4.shared.b16 {%0,%1,%2,%3}, [%4];" \
        : "=r"((r)[0]), "=r"((r)[1]), "=r"((r)[2]), "=r"((r)[3]) : "r"(addr))

// -------------------- 1: init (zero + dtype detect) --------------------------
__global__ void k_init(const void* ei_raw) {
    int i = blockIdx.x * blockDim.x + threadIdx.x;
    int stride = gridDim.x * blockDim.x;
    for (int j = i; j < N_NODES * 64; j += stride) g_acc[j] = 0.f;
    for (int j = i; j < N_NODES * 4; j += stride) g_denom[j] = 0.f;
    if (i == 0) {
        const int* p = (const int*)ei_raw;
        int is64 = 1;
        #pragma unroll 1
        for (int q = 0; q < 64; q++)
            if (p[2 * q + 1] != 0) { is64 = 0; break; }
        g_idx64 = is64;
    }
}

// -------------------- 2: bf16-split mma GEMM (ldmatrix) + fused attn ---------
// CTA = 128 rows x 64 cols, full K=128 in SMEM as bf16 hi/lo tiles.
// 512 threads, 4x4 warp grid, 32x16 warp tiles, 2 CTAs/SM.
// grid.y 0..3 -> W heads, 4 -> res_W.
// C = Ahi*Bhi + Alo*Bhi + Ahi*Blo  (residual ~2^-17).
#define LB 136
#define GM_SMEM ((128 * LB * 2 + 64 * LB * 2) * 2)   // 104448 bytes

__device__ __forceinline__ uint32_t pack_bf2(__nv_bfloat16 a, __nv_bfloat16 b) {
    return ((uint32_t)__bfloat16_as_ushort(b) << 16) | __bfloat16_as_ushort(a);
}

__device__ __forceinline__ void bf16split4(float4 v, uint2& hi, uint2& lo) {
    __nv_bfloat16 h0 = __float2bfloat16_rn(v.x);
    __nv_bfloat16 h1 = __float2bfloat16_rn(v.y);
    __nv_bfloat16 h2 = __float2bfloat16_rn(v.z);
    __nv_bfloat16 h3 = __float2bfloat16_rn(v.w);
    __nv_bfloat16 l0 = __float2bfloat16_rn(v.x - __bfloat162float(h0));
    __nv_bfloat16 l1 = __float2bfloat16_rn(v.y - __bfloat162float(h1));
    __nv_bfloat16 l2 = __float2bfloat16_rn(v.z - __bfloat162float(h2));
    __nv_bfloat16 l3 = __float2bfloat16_rn(v.w - __bfloat162float(h3));
    hi.x = pack_bf2(h0, h1); hi.y = pack_bf2(h2, h3);
    lo.x = pack_bf2(l0, l1); lo.y = pack_bf2(l2, l3);
}

__global__ void __launch_bounds__(512, 2) k_gemm_mma(
    const float* __restrict__ x, const float* __restrict__ W,
    const float* __restrict__ resW,
    const float* __restrict__ att_src, const float* __restrict__ att_dst)
{
    extern __shared__ __align__(16) __nv_bfloat16 sm[];
    __nv_bfloat16* Ahi = sm;
    __nv_bfloat16* Alo = Ahi + 128 * LB;
    __nv_bfloat16* Bhi = Alo + 128 * LB;
    __nv_bfloat16* Blo = Bhi + 64 * LB;
    int tid = threadIdx.x, lane = tid & 31, wid = tid >> 5;
    int warp_m = wid >> 2, warp_n = wid & 3;   // 4x4 warps: 32x16 warp tiles
    int m0 = blockIdx.x * 128;
    int by = blockIdx.y;

    for (int t = tid; t < 4096; t += 512) {
        int row = t >> 5, c4 = (t & 31) << 2;
        float4 v = make_float4(0.f, 0.f, 0.f, 0.f);
        int m = m0 + row;
        if (m < N_NODES) v = *(const float4*)&x[(size_t)m * 128 + c4];
        uint2 hi, lo; bf16split4(v, hi, lo);
        *(uint2*)&Ahi[row * LB + c4] = hi;
        *(uint2*)&Alo[row * LB + c4] = lo;
    }
    const float* Bsrc = (by < 4) ? (W + (size_t)by * 64 * 128) : resW;
    for (int t = tid; t < 2048; t += 512) {
        int row = t >> 5, c4 = (t & 31) << 2;
        float4 v = *(const float4*)&Bsrc[(size_t)row * 128 + c4];
        uint2 hi, lo; bf16split4(v, hi, lo);
        *(uint2*)&Bhi[row * LB + c4] = hi;
        *(uint2*)&Blo[row * LB + c4] = lo;
    }
    __syncthreads();

    float acc[2][2][4];
    #pragma unroll
    for (int i = 0; i < 2; i++)
        #pragma unroll
        for (int j = 0; j < 2; j++)
            #pragma unroll
            for (int q = 0; q < 4; q++) acc[i][j][q] = 0.f;

    // ldmatrix lane addressing
    uint32_t sb = smem_u32(sm);
    const uint32_t oAlo = 128 * LB * 2;
    const uint32_t oBhi = 256 * LB * 2;
    const uint32_t oBlo = 320 * LB * 2;
    // A: lanes 0-15 -> rows (base..base+15) @k0; lanes 16-31 -> same rows @k0+8
    int rowA = warp_m * 32 + (lane & 15);
    int kA = (lane >> 4) << 3;
    uint32_t aA0h = sb + (uint32_t)((rowA * LB + kA) * 2);          // fm=0 hi
    uint32_t aA1h = aA0h + 16 * LB * 2;                             // fm=1 hi
    uint32_t aA0l = aA0h + oAlo;
    uint32_t aA1l = aA1h + oAlo;
    // B: grp0 -> n0-7@k0, grp1 -> n0-7@k0+8, grp2 -> n8-15@k0, grp3 -> n8-15@k0+8
    int grp = lane >> 3;
    int rowB = warp_n * 16 + ((grp >> 1) << 3) + (lane & 7);
    int kB = (grp & 1) << 3;
    uint32_t aBh = sb + oBhi + (uint32_t)((rowB * LB + kB) * 2);
    uint32_t aBl = sb + oBlo + (uint32_t)((rowB * LB + kB) * 2);

    #pragma unroll
    for (int kc = 0; kc < 8; kc++) {
        uint32_t kk = kc * 32;   // 16 bf16 = 32 bytes per kc step
        uint32_t h0[4], h1[4], l0[4], l1[4], vb[4], wb[4];
        LDSM_X4(h0, aA0h + kk);
        LDSM_X4(h1, aA1h + kk);
        LDSM_X4(l0, aA0l + kk);
        LDSM_X4(l1, aA1l + kk);
        LDSM_X4(vb, aBh + kk);
        LDSM_X4(wb, aBl + kk);
        uint32_t bh0[2] = { vb[0], vb[1] }, bh1[2] = { vb[2], vb[3] };
        uint32_t bl0[2] = { wb[0], wb[1] }, bl1[2] = { wb[2], wb[3] };
        MMA_BF16(acc[0][0], l0, bh0); MMA_BF16(acc[0][0], h0, bl0); MMA_BF16(acc[0][0], h0, bh0);
        MMA_BF16(acc[0][1], l0, bh1); MMA_BF16(acc[0][1], h0, bl1); MMA_BF16(acc[0][1], h0, bh1);
        MMA_BF16(acc[1][0], l1, bh0); MMA_BF16(acc[1][0], h1, bl0); MMA_BF16(acc[1][0], h1, bh0);
        MMA_BF16(acc[1][1], l1, bh1); MMA_BF16(acc[1][1], h1, bl1); MMA_BF16(acc[1][1], h1, bh1);
    }
    __syncthreads();

    // Epilogue: bf16-packed xl stores (heads) / fp32 resid + fused attn logits.
    float* s_as = (float*)sm;
    float* s_ad = s_as + 128;
    if (by < 4) {
        if (tid < 128) { s_as[tid] = 0.f; s_ad[tid] = 0.f; }
        __syncthreads();
    }
    int g = lane >> 2, t4 = lane & 3;
    int cbase = warp_n * 16 + t4 * 2;
    #pragma unroll
    for (int fm = 0; fm < 2; fm++) {
        #pragma unroll
        for (int rs = 0; rs < 2; rs++) {
            int rloc = warp_m * 32 + fm * 16 + g + rs * 8;
            int m = m0 + rloc;
            bool ok = (m < N_NODES);
            float ps = 0.f, pd = 0.f;
            #pragma unroll
            for (int fn = 0; fn < 2; fn++) {
                float v0 = acc[fm][fn][rs * 2 + 0];
                float v1 = acc[fm][fn][rs * 2 + 1];
                int cl = cbase + fn * 8;
                if (ok) {
                    if (by < 4) {
                        uint32_t pk = pack_bf2(__float2bfloat16_rn(v0),
                                               __float2bfloat16_rn(v1));
                        *(uint32_t*)&g_xl[(size_t)m * 256 + by * 64 + cl] = pk;
                    } else {
                        g_resid[(size_t)m * 64 + cl]     = v0;
                        g_resid[(size_t)m * 64 + cl + 1] = v1;
                    }
                }
                if (by < 4) {
                    ps += v0 * att_src[by * 64 + cl] + v1 * att_src[by * 64 + cl + 1];
                    pd += v0 * att_dst[by * 64 + cl] + v1 * att_dst[by * 64 + cl + 1];
                }
            }
            if (by < 4) { atomicAdd(&s_as[rloc], ps); atomicAdd(&s_ad[rloc], pd); }
        }
    }
    if (by < 4) {
        __syncthreads();
        if (tid < 128) {
            int m = m0 + tid;
            if (m < N_NODES) {
                g_asrc[m * 4 + by] = s_as[tid];
                g_adst[m * 4 + by] = s_ad[tid];
            }
        }
    }
}

// -------------------- 3: edge pass A: exp + segment-sum denominator ----------
__global__ void __launch_bounds__(256) k_edge_exp(const void* __restrict__ ei) {
    int e = blockIdx.x * blockDim.x + threadIdx.x;
    if (e >= NE) return;
    int s, d;
    if (e < E_EDGES) { s = load_idx(ei, e); d = load_idx(ei, (long long)E_EDGES + e); }
    else             { s = d = e - E_EDGES; }
    float4 as = *(const float4*)&g_asrc[s * 4];
    float4 ad = *(const float4*)&g_adst[d * 4];
    float a0 = as.x + ad.x; a0 = a0 > 0.f ? a0 : NEG_SLOPE * a0;
    float a1 = as.y + ad.y; a1 = a1 > 0.f ? a1 : NEG_SLOPE * a1;
    float a2 = as.z + ad.z; a2 = a2 > 0.f ? a2 : NEG_SLOPE * a2;
    float a3 = as.w + ad.w; a3 = a3 > 0.f ? a3 : NEG_SLOPE * a3;
    red_add_v4(&g_denom[d * 4], expf(a0), expf(a1), expf(a2), expf(a3));
}

// -------------------- 4: edge pass B: bf16 gather + head-folded scatter ------
// (launch #4 -> gets the ncu capture this round)
// Half-warp per edge; lane ln handles channels 4*ln..4*ln+3 (512B/edge gather).
__global__ void __launch_bounds__(256) k_edge_agg(const void* __restrict__ ei) {
    long long gw = ((long long)blockIdx.x * 256 + threadIdx.x) >> 5;
    int lane = threadIdx.x & 31;
    long long e = gw * 2 + (lane >> 4);
    if (e >= NE) return;
    int ln = lane & 15;
    int s, d;
    if (e < E_EDGES) { s = load_idx(ei, e); d = load_idx(ei, E_EDGES + e); }
    else             { s = d = (int)(e - E_EDGES); }
    float4 as = *(const float4*)&g_asrc[s * 4];
    float4 ad = *(const float4*)&g_adst[d * 4];
    float a0 = as.x + ad.x; a0 = a0 > 0.f ? a0 : NEG_SLOPE * a0;
    float a1 = as.y + ad.y; a1 = a1 > 0.f ? a1 : NEG_SLOPE * a1;
    float a2 = as.z + ad.z; a2 = a2 > 0.f ? a2 : NEG_SLOPE * a2;
    float a3 = as.w + ad.w; a3 = a3 > 0.f ? a3 : NEG_SLOPE * a3;
    float4 dn = *(const float4*)&g_denom[d * 4];
    float c0 = expf(a0) / dn.x, c1 = expf(a1) / dn.y;
    float c2 = expf(a2) / dn.z, c3 = expf(a3) / dn.w;
    const __nv_bfloat16* xr = &g_xl[(size_t)s * 256];
    uint2 u0 = *(const uint2*)&xr[ln * 4];
    uint2 u1 = *(const uint2*)&xr[64 + ln * 4];
    uint2 u2 = *(const uint2*)&xr[128 + ln * 4];
    uint2 u3 = *(const uint2*)&xr[192 + ln * 4];
    float2 p0a = __bfloat1622float2(*(const __nv_bfloat162*)&u0.x);
    float2 p0b = __bfloat1622float2(*(const __nv_bfloat162*)&u0.y);
    float2 p1a = __bfloat1622float2(*(const __nv_bfloat162*)&u1.x);
    float2 p1b = __bfloat1622float2(*(const __nv_bfloat162*)&u1.y);
    float2 p2a = __bfloat1622float2(*(const __nv_bfloat162*)&u2.x);
    float2 p2b = __bfloat1622float2(*(const __nv_bfloat162*)&u2.y);
    float2 p3a = __bfloat1622float2(*(const __nv_bfloat162*)&u3.x);
    float2 p3b = __bfloat1622float2(*(const __nv_bfloat162*)&u3.y);
    red_add_v4(&g_acc[(size_t)d * 64 + ln * 4],
               c0 * p0a.x + c1 * p1a.x + c2 * p2a.x + c3 * p3a.x,
               c0 * p0a.y + c1 * p1a.y + c2 * p2a.y + c3 * p3a.y,
               c0 * p0b.x + c1 * p1b.x + c2 * p2b.x + c3 * p3b.x,
               c0 * p0b.y + c1 * p1b.y + c2 * p2b.y + c3 * p3b.y);
}

// -------------------- 5: h = acc/H + bias_gat + residual + res_b -------------
__global__ void __launch_bounds__(256) k_hcompute(const float* __restrict__ bias_gat,
                                                  const float* __restrict__ res_b) {
    int i = blockIdx.x * blockDim.x + threadIdx.x;
    if (i >= N_NODES * 64) return;
    int c = i & 63;
    g_acc[i] = g_acc[i] * 0.25f + bias_gat[c] + g_resid[i] + res_b[c];
}

// -------------------- 6: batch segment boundaries ----------------------------
__global__ void __launch_bounds__(256) k_bounds(const void* __restrict__ batch) {
    int n = blockIdx.x * blockDim.x + threadIdx.x;
    if (n >= N_NODES) return;
    int bn = load_idx(batch, n);
    if (n == 0) {
        for (int b = 0; b <= bn; b++) g_start[b] = 0;
    } else {
        int pb = load_idx(batch, n - 1);
        for (int b = pb + 1; b <= bn; b++) g_start[b] = n;
    }
    if (n == N_NODES - 1)
        for (int b = bn + 1; b <= B_GRAPHS; b++) g_start[b] = N_NODES;
}

// -------------------- 7: per-graph per-channel stats --------------------------
__global__ void __launch_bounds__(512) k_stats(const float* __restrict__ gn_mean_scale) {
    int b = blockIdx.x;
    int t = threadIdx.x;
    int c = t & 63, g = t >> 6;
    int s0 = g_start[b], s1 = g_start[b + 1];
    float sum = 0.f, sq = 0.f;
    for (int n = s0 + g; n < s1; n += 8) {
        float v = g_acc[(size_t)n * 64 + c];
        sum += v; sq += v * v;
    }
    __shared__ float sh[512], sh2[512];
    sh[t] = sum; sh2[t] = sq;
    __syncthreads();
    if (g == 0) {
        #pragma unroll
        for (int k = 1; k < 8; k++) { sum += sh[k * 64 + c]; sq += sh2[k * 64 + c]; }
        float cnt = (float)(s1 - s0);
        if (cnt > 0.f) {
            float mean = sum / cnt;
            float ms = mean * gn_mean_scale[c];
            float var = sq / cnt - 2.f * ms * mean + ms * ms;
            g_ms[b * 64 + c] = ms;
            g_inv[b * 64 + c] = rsqrtf(var + EPS_GN);
        }
    }
}

// -------------------- 8: normalize + tanh-GELU -------------------------------
__global__ void __launch_bounds__(256) k_norm(const void* __restrict__ batch,
                                              const float* __restrict__ gn_w,
                                              const float* __restrict__ gn_b,
                                              float* __restrict__ out) {
    int i = blockIdx.x * blockDim.x + threadIdx.x;
    if (i >= N_NODES * 64) return;
    int n = i >> 6, c = i & 63;
    int b = load_idx(batch, n);
    float cent = g_acc[i] - g_ms[b * 64 + c];
    float y = gn_w[c] * cent * g_inv[b * 64 + c] + gn_b[c];
    float t = tanhf(0.7978845608028654f * (y + 0.044715f * y * y * y));
    out[i] = 0.5f * y * (1.f + t);
}

// -------------------- launch --------------------------------------------------
extern "C" void kernel_launch(void* const* d_in, const int* in_sizes, int n_in,
                              void* d_out, int out_size) {
    const float* x        = (const float*)d_in[0];
    const void*  ei       = d_in[1];
    const void*  batch    = d_in[2];
    const float* W        = (const float*)d_in[3];
    const float* att_src  = (const float*)d_in[4];
    const float* att_dst  = (const float*)d_in[5];
    const float* bias_gat = (const float*)d_in[6];
    const float* res_W    = (const float*)d_in[7];
    const float* res_b    = (const float*)d_in[8];
    const float* gn_w     = (const float*)d_in[9];
    const float* gn_b     = (const float*)d_in[10];
    const float* gn_msc   = (const float*)d_in[11];
    float* out = (float*)d_out;

    cudaFuncSetAttribute(k_gemm_mma, cudaFuncAttributeMaxDynamicSharedMemorySize, GM_SMEM);

    k_init<<<2048, 256>>>(ei);                                  // 1

    dim3 ggrid((N_NODES + 127) / 128, 5);
    k_gemm_mma<<<ggrid, 512, GM_SMEM>>>(x, W, res_W, att_src, att_dst);  // 2

    k_edge_exp<<<(NE + 255) / 256, 256>>>(ei);                  // 3
    k_edge_agg<<<(NE / 2 + 7) / 8, 256>>>(ei);                  // 4 <- profiled

    k_hcompute<<<(N_NODES * 64 + 255) / 256, 256>>>(bias_gat, res_b);
    k_bounds<<<(N_NODES + 255) / 256, 256>>>(batch);
    k_stats<<<B_GRAPHS, 512>>>(gn_msc);
    k_norm<<<(N_NODES * 64 + 255) / 256, 256>>>(batch, gn_w, gn_b, out);
}

// round 17
// speedup vs baseline: 1.4835x; 1.0599x over previous
#include <cuda_runtime.h>
#include <cuda_bf16.h>
#include <cstdint>

// Problem constants
#define N_NODES 100000
#define F_INPUT 128
#define E_EDGES 1200000
#define B_GRAPHS 8
#define NE      (E_EDGES + N_NODES)   // 1,300,000 (even: 2 edges/warp exact)
#define NEG_SLOPE 0.2f
#define EPS_GN   1e-5f

// -------------------- scratch (static device globals; no allocs) ------------
__device__ __nv_bfloat16 g_xl[N_NODES * 256];   // [N, H*C] bf16 (51.2 MB)
__device__ float g_resid[N_NODES * 64];         // x @ res_W^T (fp32)
__device__ float g_asrc[N_NODES * 4];
__device__ float g_adst[N_NODES * 4];
__device__ float g_denom[N_NODES * 4];
__device__ float g_acc[N_NODES * 64];
__device__ int   g_start[B_GRAPHS + 1];
__device__ float g_ms[B_GRAPHS * 64];
__device__ float g_inv[B_GRAPHS * 64];
__device__ int   g_idx64;

// -------------------- generic helpers ---------------------------------------
__device__ __forceinline__ int load_idx(const void* p, long long i) {
    if (g_idx64) return (int)((const long long*)p)[i];
    return ((const int*)p)[i];
}

__device__ __forceinline__ void red_add_v4(float* p, float a, float b, float c, float d) {
    asm volatile("red.global.add.v4.f32 [%0], {%1, %2, %3, %4};"
                 :: "l"(p), "f"(a), "f"(b), "f"(c), "f"(d) : "memory");
}

__device__ __forceinline__ uint32_t smem_u32(const void* p) {
    uint32_t a;
    asm("{ .reg .u64 t; cvta.to.shared.u64 t, %1; cvt.u32.u64 %0, t; }" : "=r"(a) : "l"(p));
    return a;
}

// m16n8k16 bf16 mma (legacy tensor path; sm_80+ PTX)
#define MMA_BF16(c, a, b) \
    asm volatile("mma.sync.aligned.m16n8k16.row.col.f32.bf16.bf16.f32 " \
        "{%0,%1,%2,%3}, {%4,%5,%6,%7}, {%8,%9}, {%0,%1,%2,%3};" \
        : "+f"((c)[0]), "+f"((c)[1]), "+f"((c)[2]), "+f"((c)[3]) \
        : "r"((a)[0]), "r"((a)[1]), "r"((a)[2]), "r"((a)[3]), \
          "r"((b)[0]), "r"((b)[1]))

// ldmatrix 4x 8x8 b16 tiles (sm_75+)
#define LDSM_X4(r, addr) \
    asm volatile("ldmatrix.sync.aligned.m8n8.x4.shared.b16 {%0,%1,%2,%3}, [%4];" \
        : "=r"((r)[0]), "=r"((r)[1]), "=r"((r)[2]), "=r"((r)[3]) : "r"(addr))

// -------------------- 1: init (zero + dtype detect) --------------------------
__global__ void k_init(const void* ei_raw) {
    int i = blockIdx.x * blockDim.x + threadIdx.x;
    int stride = gridDim.x * blockDim.x;
    for (int j = i; j < N_NODES * 64; j += stride) g_acc[j] = 0.f;
    for (int j = i; j < N_NODES * 4; j += stride) g_denom[j] = 0.f;
    if (i == 0) {
        const int* p = (const int*)ei_raw;
        int is64 = 1;
        #pragma unroll 1
        for (int q = 0; q < 64; q++)
            if (p[2 * q + 1] != 0) { is64 = 0; break; }
        g_idx64 = is64;
    }
}

// -------------------- 2: bf16-split mma GEMM (ldmatrix) + fused attn ---------
// CTA = 128 rows x 64 cols, full K=128 in SMEM as bf16 hi/lo tiles.
// 512 threads, 4x4 warp grid, 32x16 warp tiles, 2 CTAs/SM.
// grid.y 0..3 -> W heads, 4 -> res_W.
// C = Ahi*Bhi + Alo*Bhi + Ahi*Blo  (residual ~2^-17).
#define LB 136
#define GM_SMEM ((128 * LB * 2 + 64 * LB * 2) * 2)   // 104448 bytes

__device__ __forceinline__ uint32_t pack_bf2(__nv_bfloat16 a, __nv_bfloat16 b) {
    return ((uint32_t)__bfloat16_as_ushort(b) << 16) | __bfloat16_as_ushort(a);
}

__device__ __forceinline__ void bf16split4(float4 v, uint2& hi, uint2& lo) {
    __nv_bfloat16 h0 = __float2bfloat16_rn(v.x);
    __nv_bfloat16 h1 = __float2bfloat16_rn(v.y);
    __nv_bfloat16 h2 = __float2bfloat16_rn(v.z);
    __nv_bfloat16 h3 = __float2bfloat16_rn(v.w);
    __nv_bfloat16 l0 = __float2bfloat16_rn(v.x - __bfloat162float(h0));
    __nv_bfloat16 l1 = __float2bfloat16_rn(v.y - __bfloat162float(h1));
    __nv_bfloat16 l2 = __float2bfloat16_rn(v.z - __bfloat162float(h2));
    __nv_bfloat16 l3 = __float2bfloat16_rn(v.w - __bfloat162float(h3));
    hi.x = pack_bf2(h0, h1); hi.y = pack_bf2(h2, h3);
    lo.x = pack_bf2(l0, l1); lo.y = pack_bf2(l2, l3);
}

__global__ void __launch_bounds__(512, 2) k_gemm_mma(
    const float* __restrict__ x, const float* __restrict__ W,
    const float* __restrict__ resW,
    const float* __restrict__ att_src, const float* __restrict__ att_dst)
{
    extern __shared__ __align__(16) __nv_bfloat16 sm[];
    __nv_bfloat16* Ahi = sm;
    __nv_bfloat16* Alo = Ahi + 128 * LB;
    __nv_bfloat16* Bhi = Alo + 128 * LB;
    __nv_bfloat16* Blo = Bhi + 64 * LB;
    int tid = threadIdx.x, lane = tid & 31, wid = tid >> 5;
    int warp_m = wid >> 2, warp_n = wid & 3;   // 4x4 warps: 32x16 warp tiles
    int m0 = blockIdx.x * 128;
    int by = blockIdx.y;

    for (int t = tid; t < 4096; t += 512) {
        int row = t >> 5, c4 = (t & 31) << 2;
        float4 v = make_float4(0.f, 0.f, 0.f, 0.f);
        int m = m0 + row;
        if (m < N_NODES) v = *(const float4*)&x[(size_t)m * 128 + c4];
        uint2 hi, lo; bf16split4(v, hi, lo);
        *(uint2*)&Ahi[row * LB + c4] = hi;
        *(uint2*)&Alo[row * LB + c4] = lo;
    }
    const float* Bsrc = (by < 4) ? (W + (size_t)by * 64 * 128) : resW;
    for (int t = tid; t < 2048; t += 512) {
        int row = t >> 5, c4 = (t & 31) << 2;
        float4 v = *(const float4*)&Bsrc[(size_t)row * 128 + c4];
        uint2 hi, lo; bf16split4(v, hi, lo);
        *(uint2*)&Bhi[row * LB + c4] = hi;
        *(uint2*)&Blo[row * LB + c4] = lo;
    }
    __syncthreads();

    float acc[2][2][4];
    #pragma unroll
    for (int i = 0; i < 2; i++)
        #pragma unroll
        for (int j = 0; j < 2; j++)
            #pragma unroll
            for (int q = 0; q < 4; q++) acc[i][j][q] = 0.f;

    // ldmatrix lane addressing
    uint32_t sb = smem_u32(sm);
    const uint32_t oAlo = 128 * LB * 2;
    const uint32_t oBhi = 256 * LB * 2;
    const uint32_t oBlo = 320 * LB * 2;
    int rowA = warp_m * 32 + (lane & 15);
    int kA = (lane >> 4) << 3;
    uint32_t aA0h = sb + (uint32_t)((rowA * LB + kA) * 2);
    uint32_t aA1h = aA0h + 16 * LB * 2;
    uint32_t aA0l = aA0h + oAlo;
    uint32_t aA1l = aA1h + oAlo;
    int grp = lane >> 3;
    int rowB = warp_n * 16 + ((grp >> 1) << 3) + (lane & 7);
    int kB = (grp & 1) << 3;
    uint32_t aBh = sb + oBhi + (uint32_t)((rowB * LB + kB) * 2);
    uint32_t aBl = sb + oBlo + (uint32_t)((rowB * LB + kB) * 2);

    #pragma unroll
    for (int kc = 0; kc < 8; kc++) {
        uint32_t kk = kc * 32;
        uint32_t h0[4], h1[4], l0[4], l1[4], vb[4], wb[4];
        LDSM_X4(h0, aA0h + kk);
        LDSM_X4(h1, aA1h + kk);
        LDSM_X4(l0, aA0l + kk);
        LDSM_X4(l1, aA1l + kk);
        LDSM_X4(vb, aBh + kk);
        LDSM_X4(wb, aBl + kk);
        uint32_t bh0[2] = { vb[0], vb[1] }, bh1[2] = { vb[2], vb[3] };
        uint32_t bl0[2] = { wb[0], wb[1] }, bl1[2] = { wb[2], wb[3] };
        MMA_BF16(acc[0][0], l0, bh0); MMA_BF16(acc[0][0], h0, bl0); MMA_BF16(acc[0][0], h0, bh0);
        MMA_BF16(acc[0][1], l0, bh1); MMA_BF16(acc[0][1], h0, bl1); MMA_BF16(acc[0][1], h0, bh1);
        MMA_BF16(acc[1][0], l1, bh0); MMA_BF16(acc[1][0], h1, bl0); MMA_BF16(acc[1][0], h1, bh0);
        MMA_BF16(acc[1][1], l1, bh1); MMA_BF16(acc[1][1], h1, bl1); MMA_BF16(acc[1][1], h1, bh1);
    }
    __syncthreads();

    // Epilogue: bf16-packed xl stores (heads) / fp32 resid + fused attn logits.
    float* s_as = (float*)sm;
    float* s_ad = s_as + 128;
    if (by < 4) {
        if (tid < 128) { s_as[tid] = 0.f; s_ad[tid] = 0.f; }
        __syncthreads();
    }
    int g = lane >> 2, t4 = lane & 3;
    int cbase = warp_n * 16 + t4 * 2;
    #pragma unroll
    for (int fm = 0; fm < 2; fm++) {
        #pragma unroll
        for (int rs = 0; rs < 2; rs++) {
            int rloc = warp_m * 32 + fm * 16 + g + rs * 8;
            int m = m0 + rloc;
            bool ok = (m < N_NODES);
            float ps = 0.f, pd = 0.f;
            #pragma unroll
            for (int fn = 0; fn < 2; fn++) {
                float v0 = acc[fm][fn][rs * 2 + 0];
                float v1 = acc[fm][fn][rs * 2 + 1];
                int cl = cbase + fn * 8;
                if (ok) {
                    if (by < 4) {
                        uint32_t pk = pack_bf2(__float2bfloat16_rn(v0),
                                               __float2bfloat16_rn(v1));
                        *(uint32_t*)&g_xl[(size_t)m * 256 + by * 64 + cl] = pk;
                    } else {
                        g_resid[(size_t)m * 64 + cl]     = v0;
                        g_resid[(size_t)m * 64 + cl + 1] = v1;
                    }
                }
                if (by < 4) {
                    ps += v0 * att_src[by * 64 + cl] + v1 * att_src[by * 64 + cl + 1];
                    pd += v0 * att_dst[by * 64 + cl] + v1 * att_dst[by * 64 + cl + 1];
                }
            }
            if (by < 4) { atomicAdd(&s_as[rloc], ps); atomicAdd(&s_ad[rloc], pd); }
        }
    }
    if (by < 4) {
        __syncthreads();
        if (tid < 128) {
            int m = m0 + tid;
            if (m < N_NODES) {
                g_asrc[m * 4 + by] = s_as[tid];
                g_adst[m * 4 + by] = s_ad[tid];
            }
        }
    }
}

// -------------------- 3: edge pass A: exp + segment-sum denominator ----------
__global__ void __launch_bounds__(256) k_edge_exp(const void* __restrict__ ei) {
    int e = blockIdx.x * blockDim.x + threadIdx.x;
    if (e >= NE) return;
    int s, d;
    if (e < E_EDGES) { s = load_idx(ei, e); d = load_idx(ei, (long long)E_EDGES + e); }
    else             { s = d = e - E_EDGES; }
    float4 as = *(const float4*)&g_asrc[s * 4];
    float4 ad = *(const float4*)&g_adst[d * 4];
    float a0 = as.x + ad.x; a0 = a0 > 0.f ? a0 : NEG_SLOPE * a0;
    float a1 = as.y + ad.y; a1 = a1 > 0.f ? a1 : NEG_SLOPE * a1;
    float a2 = as.z + ad.z; a2 = a2 > 0.f ? a2 : NEG_SLOPE * a2;
    float a3 = as.w + ad.w; a3 = a3 > 0.f ? a3 : NEG_SLOPE * a3;
    red_add_v4(&g_denom[d * 4], expf(a0), expf(a1), expf(a2), expf(a3));
}

// -------------------- 4: edge pass B: bf16 gather + head-folded scatter ------
// (launch #4 -> ncu capture). Half-warp per edge; NE even so all lanes active.
// Coefs computed ONCE per edge in lanes (lane&16)+0..3, shfl-broadcast.
__global__ void __launch_bounds__(256) k_edge_agg(const void* __restrict__ ei) {
    long long gw = ((long long)blockIdx.x * 256 + threadIdx.x) >> 5;
    int lane = threadIdx.x & 31;
    long long e = gw * 2 + (lane >> 4);   // NE = 2 * 650000 -> always < NE
    int ln = lane & 15;
    int s, d;
    if (e < E_EDGES) { s = load_idx(ei, e); d = load_idx(ei, E_EDGES + e); }
    else             { s = d = (int)(e - E_EDGES); }

    // lanes 0-3 (and 16-19) compute the 4 head coefficients for their edge
    float coef = 0.f;
    if (ln < 4) {
        float t = g_asrc[s * 4 + ln] + g_adst[d * 4 + ln];
        t = t > 0.f ? t : NEG_SLOPE * t;
        coef = expf(t) / g_denom[d * 4 + ln];
    }
    int base = lane & 16;
    float c0 = __shfl_sync(0xffffffffu, coef, base + 0);
    float c1 = __shfl_sync(0xffffffffu, coef, base + 1);
    float c2 = __shfl_sync(0xffffffffu, coef, base + 2);
    float c3 = __shfl_sync(0xffffffffu, coef, base + 3);

    const __nv_bfloat16* xr = &g_xl[(size_t)s * 256];
    uint2 u0 = *(const uint2*)&xr[ln * 4];
    uint2 u1 = *(const uint2*)&xr[64 + ln * 4];
    uint2 u2 = *(const uint2*)&xr[128 + ln * 4];
    uint2 u3 = *(const uint2*)&xr[192 + ln * 4];
    float2 p0a = __bfloat1622float2(*(const __nv_bfloat162*)&u0.x);
    float2 p0b = __bfloat1622float2(*(const __nv_bfloat162*)&u0.y);
    float2 p1a = __bfloat1622float2(*(const __nv_bfloat162*)&u1.x);
    float2 p1b = __bfloat1622float2(*(const __nv_bfloat162*)&u1.y);
    float2 p2a = __bfloat1622float2(*(const __nv_bfloat162*)&u2.x);
    float2 p2b = __bfloat1622float2(*(const __nv_bfloat162*)&u2.y);
    float2 p3a = __bfloat1622float2(*(const __nv_bfloat162*)&u3.x);
    float2 p3b = __bfloat1622float2(*(const __nv_bfloat162*)&u3.y);
    red_add_v4(&g_acc[(size_t)d * 64 + ln * 4],
               c0 * p0a.x + c1 * p1a.x + c2 * p2a.x + c3 * p3a.x,
               c0 * p0a.y + c1 * p1a.y + c2 * p2a.y + c3 * p3a.y,
               c0 * p0b.x + c1 * p1b.x + c2 * p2b.x + c3 * p3b.x,
               c0 * p0b.y + c1 * p1b.y + c2 * p2b.y + c3 * p3b.y);
}

// -------------------- 5: h = acc/H + bias_gat + residual + res_b -------------
__global__ void __launch_bounds__(256) k_hcompute(const float* __restrict__ bias_gat,
                                                  const float* __restrict__ res_b) {
    int i = blockIdx.x * blockDim.x + threadIdx.x;
    if (i >= N_NODES * 64) return;
    int c = i & 63;
    g_acc[i] = g_acc[i] * 0.25f + bias_gat[c] + g_resid[i] + res_b[c];
}

// -------------------- 6: batch segment boundaries ----------------------------
__global__ void __launch_bounds__(256) k_bounds(const void* __restrict__ batch) {
    int n = blockIdx.x * blockDim.x + threadIdx.x;
    if (n >= N_NODES) return;
    int bn = load_idx(batch, n);
    if (n == 0) {
        for (int b = 0; b <= bn; b++) g_start[b] = 0;
    } else {
        int pb = load_idx(batch, n - 1);
        for (int b = pb + 1; b <= bn; b++) g_start[b] = n;
    }
    if (n == N_NODES - 1)
        for (int b = bn + 1; b <= B_GRAPHS; b++) g_start[b] = N_NODES;
}

// -------------------- 7: per-graph per-channel stats --------------------------
__global__ void __launch_bounds__(512) k_stats(const float* __restrict__ gn_mean_scale) {
    int b = blockIdx.x;
    int t = threadIdx.x;
    int c = t & 63, g = t >> 6;
    int s0 = g_start[b], s1 = g_start[b + 1];
    float sum = 0.f, sq = 0.f;
    for (int n = s0 + g; n < s1; n += 8) {
        float v = g_acc[(size_t)n * 64 + c];
        sum += v; sq += v * v;
    }
    __shared__ float sh[512], sh2[512];
    sh[t] = sum; sh2[t] = sq;
    __syncthreads();
    if (g == 0) {
        #pragma unroll
        for (int k = 1; k < 8; k++) { sum += sh[k * 64 + c]; sq += sh2[k * 64 + c]; }
        float cnt = (float)(s1 - s0);
        if (cnt > 0.f) {
            float mean = sum / cnt;
            float ms = mean * gn_mean_scale[c];
            float var = sq / cnt - 2.f * ms * mean + ms * ms;
            g_ms[b * 64 + c] = ms;
            g_inv[b * 64 + c] = rsqrtf(var + EPS_GN);
        }
    }
}

// -------------------- 8: normalize + tanh-GELU -------------------------------
__global__ void __launch_bounds__(256) k_norm(const void* __restrict__ batch,
                                              const float* __restrict__ gn_w,
                                              const float* __restrict__ gn_b,
                                              float* __restrict__ out) {
    int i = blockIdx.x * blockDim.x + threadIdx.x;
    if (i >= N_NODES * 64) return;
    int n = i >> 6, c = i & 63;
    int b = load_idx(batch, n);
    float cent = g_acc[i] - g_ms[b * 64 + c];
    float y = gn_w[c] * cent * g_inv[b * 64 + c] + gn_b[c];
    float t = tanhf(0.7978845608028654f * (y + 0.044715f * y * y * y));
    out[i] = 0.5f * y * (1.f + t);
}

// -------------------- launch --------------------------------------------------
extern "C" void kernel_launch(void* const* d_in, const int* in_sizes, int n_in,
                              void* d_out, int out_size) {
    const float* x        = (const float*)d_in[0];
    const void*  ei       = d_in[1];
    const void*  batch    = d_in[2];
    const float* W        = (const float*)d_in[3];
    const float* att_src  = (const float*)d_in[4];
    const float* att_dst  = (const float*)d_in[5];
    const float* bias_gat = (const float*)d_in[6];
    const float* res_W    = (const float*)d_in[7];
    const float* res_b    = (const float*)d_in[8];
    const float* gn_w     = (const float*)d_in[9];
    const float* gn_b     = (const float*)d_in[10];
    const float* gn_msc   = (const float*)d_in[11];
    float* out = (float*)d_out;

    cudaFuncSetAttribute(k_gemm_mma, cudaFuncAttributeMaxDynamicSharedMemorySize, GM_SMEM);

    k_init<<<2048, 256>>>(ei);                                  // 1

    dim3 ggrid((N_NODES + 127) / 128, 5);
    k_gemm_mma<<<ggrid, 512, GM_SMEM>>>(x, W, res_W, att_src, att_dst);  // 2

    k_edge_exp<<<(NE + 255) / 256, 256>>>(ei);                  // 3
    k_edge_agg<<<(NE / 2 + 7) / 8, 256>>>(ei);                  // 4 <- profiled

    k_hcompute<<<(N_NODES * 64 + 255) / 256, 256>>>(bias_gat, res_b);
    k_bounds<<<(N_NODES + 255) / 256, 256>>>(batch);
    k_stats<<<B_GRAPHS, 512>>>(gn_msc);
    k_norm<<<(N_NODES * 64 + 255) / 256, 256>>>(batch, gn_w, gn_b, out);
}